// round 1
// baseline (speedup 1.0000x reference)
#include <cuda_runtime.h>
#include <math.h>

// ---------------- problem constants ----------------
// B=4, N=1024, HID=1024, NH=16, DH=64, MLP=4096, BN=4096
#define BNROWS 4096
#define HIDD   1024
#define MLPD   4096

#define INV_0596 1.6778523489932886f   // 1/0.596
#define RSQRT058 1.3130643285972254f   // 1/sqrt(0.7^2+0.3^2)

// ---------------- scratch (static device globals; no allocation) ----------------
__device__ float g_s_cond[1024];
__device__ float g_s_qkv[1024];
__device__ float g_s_out[1024];
__device__ float g_s_mlp1[1024];
__device__ float g_s_mlp2[4096];
__device__ float g_gain[4 * 1024];
__device__ float g_shift[4 * 1024];
__device__ float g_xcond[BNROWS * HIDD];          // 16 MB
__device__ float g_qkv[BNROWS * 3072];            // 48 MB
__device__ float g_q[64 * 1024 * 64];             // 16 MB  [bh][n][d]
__device__ float g_k[64 * 1024 * 64];
__device__ float g_v[64 * 1024 * 64];
__device__ float g_attn[BNROWS * HIDD];           // 16 MB
__device__ float g_x1[BNROWS * HIDD];
__device__ float g_h[(size_t)BNROWS * MLPD];      // 64 MB
__device__ float g_tmp[BNROWS * HIDD];

// ---------------- helpers ----------------
__device__ __forceinline__ float block_reduce_sum(float v, float* red) {
    __syncthreads();  // protect red[] reuse across calls
    #pragma unroll
    for (int o = 16; o > 0; o >>= 1) v += __shfl_xor_sync(0xffffffffu, v, o);
    int t = threadIdx.x;
    if ((t & 31) == 0) red[t >> 5] = v;
    __syncthreads();
    if (t < 32) {
        int nw = blockDim.x >> 5;
        float r = (t < nw) ? red[t] : 0.f;
        #pragma unroll
        for (int o = 16; o > 0; o >>= 1) r += __shfl_xor_sync(0xffffffffu, r, o);
        if (t == 0) red[0] = r;
    }
    __syncthreads();
    return red[0];
}

// ---------------- K0: weight row-norm scales ----------------
// rows: [0,1024) w_cond(out=2048), [1024,2048) w_qkv(3072), [2048,3072) w_out(1024),
//       [3072,4096) w_mlp1(4096), [4096,8192) w_mlp2(out=1024, in=4096)
__global__ void scales_kernel(const float* __restrict__ wc, const float* __restrict__ wq,
                              const float* __restrict__ wo, const float* __restrict__ w1,
                              const float* __restrict__ w2) {
    int row = blockIdx.x;
    const float* w; int len; float inv_in; float* dst; int r;
    if (row < 1024)      { w = wc; len = 2048; inv_in = 1024.f; dst = g_s_cond; r = row; }
    else if (row < 2048) { w = wq; len = 3072; inv_in = 1024.f; dst = g_s_qkv;  r = row - 1024; }
    else if (row < 3072) { w = wo; len = 1024; inv_in = 1024.f; dst = g_s_out;  r = row - 2048; }
    else if (row < 4096) { w = w1; len = 4096; inv_in = 1024.f; dst = g_s_mlp1; r = row - 3072; }
    else                 { w = w2; len = 1024; inv_in = 4096.f; dst = g_s_mlp2; r = row - 4096; }
    const float* wr = w + (size_t)r * len;
    float ss = 0.f;
    for (int j = threadIdx.x; j < len; j += blockDim.x) { float v = wr[j]; ss += v * v; }
    __shared__ float red[32];
    ss = block_reduce_sum(ss, red);
    if (threadIdx.x == 0) {
        float norm = sqrtf(ss);
        dst[r] = 1.f / ((norm * sqrtf((float)len) + 1e-4f) * sqrtf(inv_in));
    }
}

// ---------------- K1: conditioning GEMM -> gain/shift ----------------
__global__ __launch_bounds__(256) void cond_kernel(const float* __restrict__ c,
                                                   const float* __restrict__ w_cond) {
    __shared__ float ccs[4 * 1024];
    int tid = threadIdx.x;
    for (int idx = tid; idx < 4096; idx += 256) {
        int b = idx >> 10, i = idx & 1023;
        float v = c[b * 1024 + i];
        float sil = v / (1.f + expf(-v)) * INV_0596;
        ccs[idx] = sil * g_s_cond[i];
    }
    __syncthreads();
    int j = blockIdx.x * 256 + tid;  // 0..2047
    float a0 = 0.f, a1 = 0.f, a2 = 0.f, a3 = 0.f;
    for (int i = 0; i < 1024; i++) {
        float w = w_cond[(size_t)i * 2048 + j];
        a0 += ccs[i] * w;
        a1 += ccs[1024 + i] * w;
        a2 += ccs[2048 + i] * w;
        a3 += ccs[3072 + i] * w;
    }
    if (j < 1024) {
        g_gain[j] = a0; g_gain[1024 + j] = a1; g_gain[2048 + j] = a2; g_gain[3072 + j] = a3;
    } else {
        int jj = j - 1024;
        g_shift[jj] = a0; g_shift[1024 + jj] = a1; g_shift[2048 + jj] = a2; g_shift[3072 + jj] = a3;
    }
}

// ---------------- K2: x_cond = pixel_norm(x)*(1+gain)+shift ----------------
__global__ __launch_bounds__(256) void xcond_kernel(const float* __restrict__ x) {
    int r = blockIdx.x; int b = r >> 10;
    const float* xr = x + (size_t)r * HIDD;
    int e = threadIdx.x * 4;
    float4 v = *(const float4*)(xr + e);
    float ss = v.x * v.x + v.y * v.y + v.z * v.z + v.w * v.w;
    __shared__ float red[32];
    ss = block_reduce_sum(ss, red);
    float rs = rsqrtf(ss * (1.f / 1024.f) + 1e-4f);
    const float* gn = g_gain + b * 1024; const float* sh = g_shift + b * 1024;
    float4 o;
    o.x = v.x * rs * (1.f + gn[e + 0]) + sh[e + 0];
    o.y = v.y * rs * (1.f + gn[e + 1]) + sh[e + 1];
    o.z = v.z * rs * (1.f + gn[e + 2]) + sh[e + 2];
    o.w = v.w * rs * (1.f + gn[e + 3]) + sh[e + 3];
    *(float4*)(g_xcond + (size_t)r * HIDD + e) = o;
}

// ---------------- generic SIMT fp32 GEMM: C = A @ (B * s[k]) ----------------
// A[M,K] row-major, B[K,N] row-major, per-k scale s. Tile 128x128x16, 256 thr, 8x8 micro.
__global__ __launch_bounds__(256) void gemm_kernel(const float* __restrict__ A,
                                                   const float* __restrict__ B,
                                                   const float* __restrict__ s,
                                                   float* __restrict__ C,
                                                   int M, int N, int K) {
    __shared__ float sA[16][128];
    __shared__ float sB[16][128];
    int tid = threadIdx.x;
    int bm = blockIdx.y * 128;
    int bn = blockIdx.x * 128;
    int tm = (tid >> 4) << 3;
    int tn = (tid & 15) << 3;
    float acc[8][8];
    #pragma unroll
    for (int i = 0; i < 8; i++)
        #pragma unroll
        for (int j = 0; j < 8; j++) acc[i][j] = 0.f;

    for (int k0 = 0; k0 < K; k0 += 16) {
        #pragma unroll
        for (int i = 0; i < 2; i++) {
            int lid = tid + 256 * i;
            int row = lid >> 2, kc = (lid & 3) << 2;
            float4 v = *(const float4*)(A + (size_t)(bm + row) * K + k0 + kc);
            sA[kc + 0][row] = v.x; sA[kc + 1][row] = v.y;
            sA[kc + 2][row] = v.z; sA[kc + 3][row] = v.w;
        }
        #pragma unroll
        for (int i = 0; i < 2; i++) {
            int lid = tid + 256 * i;
            int kk = lid >> 5, nc = (lid & 31) << 2;
            float sk = __ldg(s + k0 + kk);
            float4 v = *(const float4*)(B + (size_t)(k0 + kk) * N + bn + nc);
            v.x *= sk; v.y *= sk; v.z *= sk; v.w *= sk;
            *(float4*)(&sB[kk][nc]) = v;
        }
        __syncthreads();
        #pragma unroll
        for (int kk = 0; kk < 16; kk++) {
            float a[8], b[8];
            *(float4*)(a)     = *(const float4*)(&sA[kk][tm]);
            *(float4*)(a + 4) = *(const float4*)(&sA[kk][tm + 4]);
            *(float4*)(b)     = *(const float4*)(&sB[kk][tn]);
            *(float4*)(b + 4) = *(const float4*)(&sB[kk][tn + 4]);
            #pragma unroll
            for (int i = 0; i < 8; i++)
                #pragma unroll
                for (int j = 0; j < 8; j++) acc[i][j] += a[i] * b[j];
        }
        __syncthreads();
    }
    #pragma unroll
    for (int i = 0; i < 8; i++) {
        float* cp = C + (size_t)(bm + tm + i) * N + bn + tn;
        float4 o0 = {acc[i][0], acc[i][1], acc[i][2], acc[i][3]};
        float4 o1 = {acc[i][4], acc[i][5], acc[i][6], acc[i][7]};
        *(float4*)(cp) = o0;
        *(float4*)(cp + 4) = o1;
    }
}

// ---------------- K3: q/k/v normalization + head-major layout ----------------
__global__ __launch_bounds__(256) void qkvnorm_kernel() {
    int r = blockIdx.x; int b = r >> 10, n = r & 1023;
    const float* row = g_qkv + (size_t)r * 3072;
    int t = threadIdx.x, e = t * 4, head = t >> 4;
    float4 q = *(const float4*)(row + e);
    float4 k = *(const float4*)(row + 1024 + e);
    float4 v = *(const float4*)(row + 2048 + e);
    __shared__ float hq[16], hk[16], hv[16];
    if (t < 16) { hq[t] = 0.f; hk[t] = 0.f; hv[t] = 0.f; }
    __syncthreads();
    float sq = q.x * q.x + q.y * q.y + q.z * q.z + q.w * q.w;
    float sk = k.x * k.x + k.y * k.y + k.z * k.z + k.w * k.w;
    float sv = v.x * v.x + v.y * v.y + v.z * v.z + v.w * v.w;
    atomicAdd(&hq[head], sq); atomicAdd(&hk[head], sk); atomicAdd(&hv[head], sv);
    __syncthreads();
    float tq = 0.f, tk = 0.f, tv = 0.f;
    #pragma unroll
    for (int h = 0; h < 16; h++) { tq += hq[h]; tk += hk[h]; tv += hv[h]; }
    float pq = rsqrtf(tq * (1.f / 1024.f) + 1e-4f);
    float pk = rsqrtf(tk * (1.f / 1024.f) + 1e-4f);
    float pv = rsqrtf(tv * (1.f / 1024.f) + 1e-4f);
    float qs = pq * rsqrtf(pq * pq * hq[head] + 1e-6f) * 0.125f;  // fold 1/sqrt(DH)
    float ks = pk * rsqrtf(pk * pk * hk[head] + 1e-6f);
    size_t base = ((size_t)(b * 16 + head) * 1024 + n) * 64 + (e & 63);
    float4 oq = {q.x * qs, q.y * qs, q.z * qs, q.w * qs};
    float4 ok = {k.x * ks, k.y * ks, k.z * ks, k.w * ks};
    float4 ov = {v.x * pv, v.y * pv, v.z * pv, v.w * pv};
    *(float4*)(g_q + base) = oq;
    *(float4*)(g_k + base) = ok;
    *(float4*)(g_v + base) = ov;
}

// ---------------- K4: flash attention (fp32 SIMT) ----------------
// grid (16 qtiles, 64 bh), 128 threads. Per block: 64 queries, K/V tiles of 64.
// smem: sQt[64][64] (d-major), sKtP[64][68] (Kt then P, shared), sV[64][64].
#define ATT_SMEM_FLOATS (64 * 64 + 64 * 68 + 64 * 64)
__global__ __launch_bounds__(128) void attn_kernel() {
    extern __shared__ float sm[];
    float* sQt  = sm;                 // [d][q]
    float* sKtP = sm + 64 * 64;       // [d][m] (stride 68) / later [m][q] (stride 68)
    float* sV   = sKtP + 64 * 68;     // [m][d]
    int tid = threadIdx.x;
    int bh = blockIdx.y;
    int n0 = blockIdx.x * 64;
    const float* qb = g_q + ((size_t)bh * 1024 + n0) * 64;
    const float* kb = g_k + (size_t)bh * 1024 * 64;
    const float* vb = g_v + (size_t)bh * 1024 * 64;

    for (int lid = tid; lid < 64 * 16; lid += 128) {
        int q = lid >> 4, dc = (lid & 15) * 4;
        float4 v = *(const float4*)(qb + q * 64 + dc);
        sQt[(dc + 0) * 64 + q] = v.x; sQt[(dc + 1) * 64 + q] = v.y;
        sQt[(dc + 2) * 64 + q] = v.z; sQt[(dc + 3) * 64 + q] = v.w;
    }
    int tm = tid & 7, tq = tid >> 3;  // tm: 8 key/d groups, tq: 16 query groups of 4
    float acc[4][8];
    #pragma unroll
    for (int i = 0; i < 4; i++)
        #pragma unroll
        for (int j = 0; j < 8; j++) acc[i][j] = 0.f;
    float mi[4] = {-INFINITY, -INFINITY, -INFINITY, -INFINITY};
    float li[4] = {0.f, 0.f, 0.f, 0.f};

    for (int kt = 0; kt < 16; kt++) {
        __syncthreads();  // prev PV readers done
        const float* kb0 = kb + (size_t)kt * 64 * 64;
        const float* vb0 = vb + (size_t)kt * 64 * 64;
        for (int lid = tid; lid < 64 * 16; lid += 128) {
            int m = lid >> 4, dc = (lid & 15) * 4;
            float4 v = *(const float4*)(kb0 + m * 64 + dc);
            sKtP[(dc + 0) * 68 + m] = v.x; sKtP[(dc + 1) * 68 + m] = v.y;
            sKtP[(dc + 2) * 68 + m] = v.z; sKtP[(dc + 3) * 68 + m] = v.w;
            *(float4*)(sV + m * 64 + dc) = *(const float4*)(vb0 + m * 64 + dc);
        }
        __syncthreads();

        float sc[4][8];
        #pragma unroll
        for (int i = 0; i < 4; i++)
            #pragma unroll
            for (int j = 0; j < 8; j++) sc[i][j] = 0.f;
        #pragma unroll 8
        for (int d = 0; d < 64; d++) {
            float4 qv = *(const float4*)(sQt + d * 64 + 4 * tq);
            float4 k0v = *(const float4*)(sKtP + d * 68 + 8 * tm);
            float4 k1v = *(const float4*)(sKtP + d * 68 + 8 * tm + 4);
            float kk[8] = {k0v.x, k0v.y, k0v.z, k0v.w, k1v.x, k1v.y, k1v.z, k1v.w};
            float qq[4] = {qv.x, qv.y, qv.z, qv.w};
            #pragma unroll
            for (int i = 0; i < 4; i++)
                #pragma unroll
                for (int j = 0; j < 8; j++) sc[i][j] += qq[i] * kk[j];
        }
        // online softmax per query row (8-lane groups share a row)
        #pragma unroll
        for (int r = 0; r < 4; r++) {
            float mx = sc[r][0];
            #pragma unroll
            for (int j = 1; j < 8; j++) mx = fmaxf(mx, sc[r][j]);
            #pragma unroll
            for (int o = 4; o > 0; o >>= 1) mx = fmaxf(mx, __shfl_xor_sync(0xffffffffu, mx, o));
            float mn = fmaxf(mi[r], mx);
            float corr = __expf(mi[r] - mn);
            float ps = 0.f;
            #pragma unroll
            for (int j = 0; j < 8; j++) { float p = __expf(sc[r][j] - mn); sc[r][j] = p; ps += p; }
            #pragma unroll
            for (int o = 4; o > 0; o >>= 1) ps += __shfl_xor_sync(0xffffffffu, ps, o);
            li[r] = li[r] * corr + ps;
            mi[r] = mn;
            #pragma unroll
            for (int j = 0; j < 8; j++) acc[r][j] *= corr;
        }
        __syncthreads();  // done reading Kt
        #pragma unroll
        for (int r = 0; r < 4; r++)
            #pragma unroll
            for (int j = 0; j < 8; j++)
                sKtP[(8 * tm + j) * 68 + 4 * tq + r] = sc[r][j];  // P[m][q]
        __syncthreads();
        #pragma unroll 8
        for (int mm = 0; mm < 64; mm++) {
            float4 pv = *(const float4*)(sKtP + mm * 68 + 4 * tq);
            float4 v0 = *(const float4*)(sV + mm * 64 + 8 * tm);
            float4 v1 = *(const float4*)(sV + mm * 64 + 8 * tm + 4);
            float vv[8] = {v0.x, v0.y, v0.z, v0.w, v1.x, v1.y, v1.z, v1.w};
            float pp[4] = {pv.x, pv.y, pv.z, pv.w};
            #pragma unroll
            for (int i = 0; i < 4; i++)
                #pragma unroll
                for (int j = 0; j < 8; j++) acc[i][j] += pp[i] * vv[j];
        }
    }
    int b = bh >> 4, h = bh & 15;
    #pragma unroll
    for (int r = 0; r < 4; r++) {
        float inv = 1.f / li[r];
        int rowg = b * 1024 + n0 + 4 * tq + r;
        float* op = g_attn + (size_t)rowg * HIDD + h * 64 + 8 * tm;
        float4 o0 = {acc[r][0] * inv, acc[r][1] * inv, acc[r][2] * inv, acc[r][3] * inv};
        float4 o1 = {acc[r][4] * inv, acc[r][5] * inv, acc[r][6] * inv, acc[r][7] * inv};
        *(float4*)(op) = o0;
        *(float4*)(op + 4) = o1;
    }
}

// ---------------- K5: attn epilogue + residual + second x_cond ----------------
__global__ __launch_bounds__(256) void post_attn_kernel(const float* __restrict__ x,
                                                        const float* __restrict__ attn_gain) {
    int r = blockIdx.x, b = r >> 10;
    int e = threadIdx.x * 4;
    float4 y = *(const float4*)(g_tmp + (size_t)r * HIDD + e);
    __shared__ float red[32];
    float ss = y.x * y.x + y.y * y.y + y.z * y.z + y.w * y.w;
    ss = block_reduce_sum(ss, red);
    float py = rsqrtf(ss * (1.f / 1024.f) + 1e-4f) * expf(attn_gain[0]);
    float4 xv = *(const float4*)(x + (size_t)r * HIDD + e);
    float4 x1;
    x1.x = (0.7f * xv.x + 0.3f * (y.x * py)) * RSQRT058;
    x1.y = (0.7f * xv.y + 0.3f * (y.y * py)) * RSQRT058;
    x1.z = (0.7f * xv.z + 0.3f * (y.z * py)) * RSQRT058;
    x1.w = (0.7f * xv.w + 0.3f * (y.w * py)) * RSQRT058;
    *(float4*)(g_x1 + (size_t)r * HIDD + e) = x1;
    float ss1 = x1.x * x1.x + x1.y * x1.y + x1.z * x1.z + x1.w * x1.w;
    ss1 = block_reduce_sum(ss1, red);
    float p1 = rsqrtf(ss1 * (1.f / 1024.f) + 1e-4f);
    const float* gn = g_gain + b * 1024; const float* sh = g_shift + b * 1024;
    float4 o;
    o.x = x1.x * p1 * (1.f + gn[e + 0]) + sh[e + 0];
    o.y = x1.y * p1 * (1.f + gn[e + 1]) + sh[e + 1];
    o.z = x1.z * p1 * (1.f + gn[e + 2]) + sh[e + 2];
    o.w = x1.w * p1 * (1.f + gn[e + 3]) + sh[e + 3];
    *(float4*)(g_xcond + (size_t)r * HIDD + e) = o;
}

// ---------------- K6: MLP hidden activation (pixel_norm + mp_silu) ----------------
__global__ __launch_bounds__(256) void mlp_act_kernel() {
    int r = blockIdx.x;
    float* row = g_h + (size_t)r * MLPD;
    float4 v[4];
    float ss = 0.f;
    #pragma unroll
    for (int i = 0; i < 4; i++) {
        v[i] = *(const float4*)(row + (threadIdx.x + 256 * i) * 4);
        ss += v[i].x * v[i].x + v[i].y * v[i].y + v[i].z * v[i].z + v[i].w * v[i].w;
    }
    __shared__ float red[32];
    ss = block_reduce_sum(ss, red);
    float ps = rsqrtf(ss * (1.f / 4096.f) + 1e-4f);
    #pragma unroll
    for (int i = 0; i < 4; i++) {
        float u0 = v[i].x * ps, u1 = v[i].y * ps, u2 = v[i].z * ps, u3 = v[i].w * ps;
        float4 o;
        o.x = u0 / (1.f + expf(-u0)) * INV_0596;
        o.y = u1 / (1.f + expf(-u1)) * INV_0596;
        o.z = u2 / (1.f + expf(-u2)) * INV_0596;
        o.w = u3 / (1.f + expf(-u3)) * INV_0596;
        *(float4*)(row + (threadIdx.x + 256 * i) * 4) = o;
    }
}

// ---------------- K7: final epilogue ----------------
__global__ __launch_bounds__(256) void final_kernel(const float* __restrict__ mlp_gain,
                                                    float* __restrict__ out) {
    int r = blockIdx.x;
    int e = threadIdx.x * 4;
    float4 y = *(const float4*)(g_tmp + (size_t)r * HIDD + e);
    __shared__ float red[32];
    float ss = y.x * y.x + y.y * y.y + y.z * y.z + y.w * y.w;
    ss = block_reduce_sum(ss, red);
    float pm = rsqrtf(ss * (1.f / 1024.f) + 1e-4f) * expf(mlp_gain[0]);
    float4 x1 = *(const float4*)(g_x1 + (size_t)r * HIDD + e);
    float4 o;
    o.x = (0.7f * x1.x + 0.3f * (y.x * pm)) * RSQRT058;
    o.y = (0.7f * x1.y + 0.3f * (y.y * pm)) * RSQRT058;
    o.z = (0.7f * x1.z + 0.3f * (y.z * pm)) * RSQRT058;
    o.w = (0.7f * x1.w + 0.3f * (y.w * pm)) * RSQRT058;
    *(float4*)(out + (size_t)r * HIDD + e) = o;
}

// ---------------- launch ----------------
extern "C" void kernel_launch(void* const* d_in, const int* in_sizes, int n_in,
                              void* d_out, int out_size) {
    const float* x        = (const float*)d_in[0];
    const float* c        = (const float*)d_in[1];
    const float* w_cond   = (const float*)d_in[2];
    const float* w_qkv    = (const float*)d_in[3];
    const float* w_out    = (const float*)d_in[4];
    const float* w_mlp1   = (const float*)d_in[5];
    const float* w_mlp2   = (const float*)d_in[6];
    const float* attn_gain = (const float*)d_in[7];
    const float* mlp_gain  = (const float*)d_in[8];
    float* out = (float*)d_out;

    void* p;
    cudaGetSymbolAddress(&p, g_xcond);  float* xcond = (float*)p;
    cudaGetSymbolAddress(&p, g_qkv);    float* qkv   = (float*)p;
    cudaGetSymbolAddress(&p, g_attn);   float* attn  = (float*)p;
    cudaGetSymbolAddress(&p, g_h);      float* hbuf  = (float*)p;
    cudaGetSymbolAddress(&p, g_tmp);    float* tmp   = (float*)p;
    cudaGetSymbolAddress(&p, g_s_qkv);  float* sqkv  = (float*)p;
    cudaGetSymbolAddress(&p, g_s_out);  float* sout  = (float*)p;
    cudaGetSymbolAddress(&p, g_s_mlp1); float* smlp1 = (float*)p;
    cudaGetSymbolAddress(&p, g_s_mlp2); float* smlp2 = (float*)p;

    cudaFuncSetAttribute(attn_kernel, cudaFuncAttributeMaxDynamicSharedMemorySize,
                         ATT_SMEM_FLOATS * (int)sizeof(float));

    scales_kernel<<<8192, 128>>>(w_cond, w_qkv, w_out, w_mlp1, w_mlp2);
    cond_kernel<<<8, 256>>>(c, w_cond);
    xcond_kernel<<<4096, 256>>>(x);
    gemm_kernel<<<dim3(3072 / 128, 4096 / 128), 256>>>(xcond, w_qkv, sqkv, qkv, 4096, 3072, 1024);
    qkvnorm_kernel<<<4096, 256>>>();
    attn_kernel<<<dim3(16, 64), 128, ATT_SMEM_FLOATS * sizeof(float)>>>();
    gemm_kernel<<<dim3(1024 / 128, 4096 / 128), 256>>>(attn, w_out, sout, tmp, 4096, 1024, 1024);
    post_attn_kernel<<<4096, 256>>>(x, attn_gain);
    gemm_kernel<<<dim3(4096 / 128, 4096 / 128), 256>>>(xcond, w_mlp1, smlp1, hbuf, 4096, 4096, 1024);
    mlp_act_kernel<<<4096, 256>>>();
    gemm_kernel<<<dim3(1024 / 128, 4096 / 128), 256>>>(hbuf, w_mlp2, smlp2, tmp, 4096, 1024, 4096);
    final_kernel<<<4096, 256>>>(mlp_gain, out);
}

// round 4
// speedup vs baseline: 1.8152x; 1.8152x over previous
#include <cuda_runtime.h>
#include <math.h>
#include <stdint.h>

// ---------------- problem constants ----------------
#define BNROWS 4096
#define HIDD   1024
#define MLPD   4096

#define INV_0596 1.6778523489932886f
#define RSQRT058 1.3130643285972254f

// ---------------- scratch ----------------
__device__ float g_s_cond[1024];
__device__ float g_s_qkv[1024];
__device__ float g_s_out[1024];
__device__ float g_s_mlp1[1024];
__device__ float g_s_mlp2[4096];
__device__ float g_gain[4 * 1024];
__device__ float g_shift[4 * 1024];
__device__ float g_xcond[BNROWS * HIDD];
__device__ float g_qkv[BNROWS * 3072];
__device__ float g_q[64 * 1024 * 64];
__device__ float g_k[64 * 1024 * 64];
__device__ float g_v[64 * 1024 * 64];
__device__ float g_attn[BNROWS * HIDD];
__device__ float g_x1[BNROWS * HIDD];
__device__ float g_h[(size_t)BNROWS * MLPD];
__device__ float g_tmp[BNROWS * HIDD];
// transposed+scaled tf32 weights [N][K]
__device__ float g_wtq[3072 * 1024];
__device__ float g_wto[1024 * 1024];
__device__ float g_wt1[4096 * 1024];
__device__ float g_wt2[1024 * 4096];

// ---------------- helpers ----------------
__device__ __forceinline__ float to_tf32(float x) {
    uint32_t u;
    asm("cvt.rna.tf32.f32 %0, %1;" : "=r"(u) : "f"(x));
    return __uint_as_float(u);
}

__device__ __forceinline__ float block_reduce_sum(float v, float* red) {
    __syncthreads();
    #pragma unroll
    for (int o = 16; o > 0; o >>= 1) v += __shfl_xor_sync(0xffffffffu, v, o);
    int t = threadIdx.x;
    if ((t & 31) == 0) red[t >> 5] = v;
    __syncthreads();
    if (t < 32) {
        int nw = blockDim.x >> 5;
        float r = (t < nw) ? red[t] : 0.f;
        #pragma unroll
        for (int o = 16; o > 0; o >>= 1) r += __shfl_xor_sync(0xffffffffu, r, o);
        if (t == 0) red[0] = r;
    }
    __syncthreads();
    return red[0];
}

__device__ __forceinline__ void cp16(uint32_t s, const void* g) {
    asm volatile("cp.async.cg.shared.global [%0], [%1], 16;" :: "r"(s), "l"(g));
}
__device__ __forceinline__ uint32_t smem_u32(const void* p) {
    uint32_t a;
    asm("{ .reg .u64 t; cvta.to.shared.u64 t, %1; cvt.u32.u64 %0, t; }" : "=r"(a) : "l"(p));
    return a;
}

__device__ __forceinline__ void mma_tf32(float* c, const uint32_t* a, const uint32_t* b) {
    asm volatile("mma.sync.aligned.m16n8k8.row.col.f32.tf32.tf32.f32 "
        "{%0,%1,%2,%3}, {%4,%5,%6,%7}, {%8,%9}, {%0,%1,%2,%3};"
        : "+f"(c[0]), "+f"(c[1]), "+f"(c[2]), "+f"(c[3])
        : "r"(a[0]), "r"(a[1]), "r"(a[2]), "r"(a[3]), "r"(b[0]), "r"(b[1]));
}

// ---------------- K0: weight row-norm scales ----------------
__global__ void scales_kernel(const float* __restrict__ wc, const float* __restrict__ wq,
                              const float* __restrict__ wo, const float* __restrict__ w1,
                              const float* __restrict__ w2) {
    int row = blockIdx.x;
    const float* w; int len; float inv_in; float* dst; int r;
    if (row < 1024)      { w = wc; len = 2048; inv_in = 1024.f; dst = g_s_cond; r = row; }
    else if (row < 2048) { w = wq; len = 3072; inv_in = 1024.f; dst = g_s_qkv;  r = row - 1024; }
    else if (row < 3072) { w = wo; len = 1024; inv_in = 1024.f; dst = g_s_out;  r = row - 2048; }
    else if (row < 4096) { w = w1; len = 4096; inv_in = 1024.f; dst = g_s_mlp1; r = row - 3072; }
    else                 { w = w2; len = 1024; inv_in = 4096.f; dst = g_s_mlp2; r = row - 4096; }
    const float* wr = w + (size_t)r * len;
    float ss = 0.f;
    for (int j = threadIdx.x; j < len; j += blockDim.x) { float v = wr[j]; ss += v * v; }
    __shared__ float red[32];
    ss = block_reduce_sum(ss, red);
    if (threadIdx.x == 0) {
        float norm = sqrtf(ss);
        dst[r] = 1.f / ((norm * sqrtf((float)len) + 1e-4f) * sqrtf(inv_in));
    }
}

// ---------------- transpose + scale-fold + tf32 round: Wt[n][k] = tf32(W[k][n]*s[k]) ----------------
__global__ __launch_bounds__(256) void transpose_scale_kernel(const float* __restrict__ W,
                                                              const float* __restrict__ s,
                                                              float* __restrict__ Wt,
                                                              int K, int N) {
    __shared__ float t[32][33];
    int k0 = blockIdx.y * 32, n0 = blockIdx.x * 32;
    int tx = threadIdx.x & 31, ty = threadIdx.x >> 5;
    #pragma unroll
    for (int i = 0; i < 32; i += 8) {
        int k = k0 + ty + i;
        t[ty + i][tx] = to_tf32(W[(size_t)k * N + n0 + tx] * s[k]);
    }
    __syncthreads();
    #pragma unroll
    for (int i = 0; i < 32; i += 8)
        Wt[(size_t)(n0 + ty + i) * K + k0 + tx] = t[tx][ty + i];
}

// ---------------- tf32 mma.sync GEMM: C[M,N] = A[M,K] @ Bt[N,K]^T ----------------
// tile 128x128x32, 256 thr (8 warps, 4M x 2N), warp tile 32x64 (2x8 m16n8k8).
// smem rows padded to 36 floats (144B, 16B aligned).
#define GS_ROW   36
#define GS_TILE  (128 * GS_ROW)              // floats per operand per stage
#define GS_STAGE (2 * GS_TILE)               // A + B
#define GEMM_SMEM_BYTES (2 * GS_STAGE * 4)
__global__ __launch_bounds__(256, 1)
void gemm_mma_kernel(const float* __restrict__ A, const float* __restrict__ Bt,
                     float* __restrict__ C, int M, int N, int K) {
    extern __shared__ float sm[];
    float* st[2];
    st[0] = sm;
    st[1] = sm + GS_STAGE;
    uint32_t sb[2] = {smem_u32(st[0]), smem_u32(st[1])};

    int tid = threadIdx.x;
    int wid = tid >> 5, lane = tid & 31;
    int g = lane >> 2, j = lane & 3;
    int wm = wid >> 1, wn = wid & 1;
    int bm = blockIdx.y * 128;
    int bn = blockIdx.x * 128;

    float acc[2][8][4];
    #pragma unroll
    for (int mt = 0; mt < 2; mt++)
        #pragma unroll
        for (int nt = 0; nt < 8; nt++)
            #pragma unroll
            for (int q = 0; q < 4; q++) acc[mt][nt][q] = 0.f;

    const int NC = K >> 5;

    auto load_chunk = [&](int c, int stg) {
        uint32_t sA = sb[stg];
        uint32_t sB = sb[stg] + GS_TILE * 4;
        int kc = c << 5;
        #pragma unroll
        for (int i = 0; i < 4; i++) {
            int seg = tid + 256 * i;
            int row = seg >> 3, k4 = seg & 7;
            cp16(sA + row * (GS_ROW * 4) + k4 * 16, A + (size_t)(bm + row) * K + kc + k4 * 4);
        }
        #pragma unroll
        for (int i = 0; i < 4; i++) {
            int seg = tid + 256 * i;
            int row = seg >> 3, k4 = seg & 7;
            cp16(sB + row * (GS_ROW * 4) + k4 * 16, Bt + (size_t)(bn + row) * K + kc + k4 * 4);
        }
    };

    load_chunk(0, 0);
    asm volatile("cp.async.commit_group;" ::: "memory");

    for (int c = 0; c < NC; c++) {
        int s = c & 1;
        if (c + 1 < NC) {
            load_chunk(c + 1, s ^ 1);
            asm volatile("cp.async.commit_group;" ::: "memory");
            asm volatile("cp.async.wait_group 1;" ::: "memory");
        } else {
            asm volatile("cp.async.wait_group 0;" ::: "memory");
        }
        __syncthreads();

        const uint32_t* uA = (const uint32_t*)st[s];
        const uint32_t* uB = (const uint32_t*)(st[s] + GS_TILE);
        #pragma unroll
        for (int ks = 0; ks < 4; ks++) {
            int k = ks * 8;
            uint32_t af[2][4];
            #pragma unroll
            for (int mt = 0; mt < 2; mt++) {
                int row = wm * 32 + mt * 16 + g;
                af[mt][0] = uA[row * GS_ROW + k + j];
                af[mt][1] = uA[(row + 8) * GS_ROW + k + j];
                af[mt][2] = uA[row * GS_ROW + k + j + 4];
                af[mt][3] = uA[(row + 8) * GS_ROW + k + j + 4];
            }
            #pragma unroll
            for (int nt = 0; nt < 8; nt++) {
                int n = wn * 64 + nt * 8 + g;
                uint32_t bf[2];
                bf[0] = uB[n * GS_ROW + k + j];
                bf[1] = uB[n * GS_ROW + k + j + 4];
                #pragma unroll
                for (int mt = 0; mt < 2; mt++)
                    mma_tf32(acc[mt][nt], af[mt], bf);
            }
        }
        __syncthreads();
    }

    #pragma unroll
    for (int mt = 0; mt < 2; mt++) {
        int row = bm + wm * 32 + mt * 16 + g;
        #pragma unroll
        for (int nt = 0; nt < 8; nt++) {
            int col = bn + wn * 64 + nt * 8 + 2 * j;
            float2 o0 = {acc[mt][nt][0], acc[mt][nt][1]};
            float2 o1 = {acc[mt][nt][2], acc[mt][nt][3]};
            *(float2*)(C + (size_t)row * N + col) = o0;
            *(float2*)(C + (size_t)(row + 8) * N + col) = o1;
        }
    }
}

// ---------------- K1: conditioning GEMM -> gain/shift ----------------
__global__ __launch_bounds__(256) void cond_kernel(const float* __restrict__ c,
                                                   const float* __restrict__ w_cond) {
    __shared__ float ccs[4 * 1024];
    int tid = threadIdx.x;
    for (int idx = tid; idx < 4096; idx += 256) {
        int b = idx >> 10, i = idx & 1023;
        float v = c[b * 1024 + i];
        float sil = v / (1.f + expf(-v)) * INV_0596;
        ccs[idx] = sil * g_s_cond[i];
    }
    __syncthreads();
    int j = blockIdx.x * 256 + tid;
    float a0 = 0.f, a1 = 0.f, a2 = 0.f, a3 = 0.f;
    for (int i = 0; i < 1024; i++) {
        float w = w_cond[(size_t)i * 2048 + j];
        a0 += ccs[i] * w; a1 += ccs[1024 + i] * w;
        a2 += ccs[2048 + i] * w; a3 += ccs[3072 + i] * w;
    }
    if (j < 1024) {
        g_gain[j] = a0; g_gain[1024 + j] = a1; g_gain[2048 + j] = a2; g_gain[3072 + j] = a3;
    } else {
        int jj = j - 1024;
        g_shift[jj] = a0; g_shift[1024 + jj] = a1; g_shift[2048 + jj] = a2; g_shift[3072 + jj] = a3;
    }
}

// ---------------- K2: x_cond (tf32-rounded output) ----------------
__global__ __launch_bounds__(256) void xcond_kernel(const float* __restrict__ x) {
    int r = blockIdx.x; int b = r >> 10;
    const float* xr = x + (size_t)r * HIDD;
    int e = threadIdx.x * 4;
    float4 v = *(const float4*)(xr + e);
    float ss = v.x * v.x + v.y * v.y + v.z * v.z + v.w * v.w;
    __shared__ float red[32];
    ss = block_reduce_sum(ss, red);
    float rs = rsqrtf(ss * (1.f / 1024.f) + 1e-4f);
    const float* gn = g_gain + b * 1024; const float* sh = g_shift + b * 1024;
    float4 o;
    o.x = to_tf32(v.x * rs * (1.f + gn[e + 0]) + sh[e + 0]);
    o.y = to_tf32(v.y * rs * (1.f + gn[e + 1]) + sh[e + 1]);
    o.z = to_tf32(v.z * rs * (1.f + gn[e + 2]) + sh[e + 2]);
    o.w = to_tf32(v.w * rs * (1.f + gn[e + 3]) + sh[e + 3]);
    *(float4*)(g_xcond + (size_t)r * HIDD + e) = o;
}

// ---------------- K3: q/k/v normalization ----------------
__global__ __launch_bounds__(256) void qkvnorm_kernel() {
    int r = blockIdx.x; int b = r >> 10, n = r & 1023;
    const float* row = g_qkv + (size_t)r * 3072;
    int t = threadIdx.x, e = t * 4, head = t >> 4;
    float4 q = *(const float4*)(row + e);
    float4 k = *(const float4*)(row + 1024 + e);
    float4 v = *(const float4*)(row + 2048 + e);
    __shared__ float hq[16], hk[16], hv[16];
    if (t < 16) { hq[t] = 0.f; hk[t] = 0.f; hv[t] = 0.f; }
    __syncthreads();
    float sq = q.x * q.x + q.y * q.y + q.z * q.z + q.w * q.w;
    float sk = k.x * k.x + k.y * k.y + k.z * k.z + k.w * k.w;
    float sv = v.x * v.x + v.y * v.y + v.z * v.z + v.w * v.w;
    atomicAdd(&hq[head], sq); atomicAdd(&hk[head], sk); atomicAdd(&hv[head], sv);
    __syncthreads();
    float tq = 0.f, tk = 0.f, tv = 0.f;
    #pragma unroll
    for (int h = 0; h < 16; h++) { tq += hq[h]; tk += hk[h]; tv += hv[h]; }
    float pq = rsqrtf(tq * (1.f / 1024.f) + 1e-4f);
    float pk = rsqrtf(tk * (1.f / 1024.f) + 1e-4f);
    float pv = rsqrtf(tv * (1.f / 1024.f) + 1e-4f);
    float qs = pq * rsqrtf(pq * pq * hq[head] + 1e-6f) * 0.125f;
    float ks = pk * rsqrtf(pk * pk * hk[head] + 1e-6f);
    size_t base = ((size_t)(b * 16 + head) * 1024 + n) * 64 + (e & 63);
    float4 oq = {q.x * qs, q.y * qs, q.z * qs, q.w * qs};
    float4 ok = {k.x * ks, k.y * ks, k.z * ks, k.w * ks};
    float4 ov = {v.x * pv, v.y * pv, v.z * pv, v.w * pv};
    *(float4*)(g_q + base) = oq;
    *(float4*)(g_k + base) = ok;
    *(float4*)(g_v + base) = ov;
}

// ---------------- K4: flash attention (fp32 SIMT, tf32-rounded output) ----------------
#define ATT_SMEM_FLOATS (64 * 64 + 64 * 68 + 64 * 64)
__global__ __launch_bounds__(128) void attn_kernel() {
    extern __shared__ float sm[];
    float* sQt  = sm;
    float* sKtP = sm + 64 * 64;
    float* sV   = sKtP + 64 * 68;
    int tid = threadIdx.x;
    int bh = blockIdx.y;
    int n0 = blockIdx.x * 64;
    const float* qb = g_q + ((size_t)bh * 1024 + n0) * 64;
    const float* kb = g_k + (size_t)bh * 1024 * 64;
    const float* vb = g_v + (size_t)bh * 1024 * 64;

    for (int lid = tid; lid < 64 * 16; lid += 128) {
        int q = lid >> 4, dc = (lid & 15) * 4;
        float4 v = *(const float4*)(qb + q * 64 + dc);
        sQt[(dc + 0) * 64 + q] = v.x; sQt[(dc + 1) * 64 + q] = v.y;
        sQt[(dc + 2) * 64 + q] = v.z; sQt[(dc + 3) * 64 + q] = v.w;
    }
    int tm = tid & 7, tq = tid >> 3;
    float acc[4][8];
    #pragma unroll
    for (int i = 0; i < 4; i++)
        #pragma unroll
        for (int j = 0; j < 8; j++) acc[i][j] = 0.f;
    float mi[4] = {-INFINITY, -INFINITY, -INFINITY, -INFINITY};
    float li[4] = {0.f, 0.f, 0.f, 0.f};

    for (int kt = 0; kt < 16; kt++) {
        __syncthreads();
        const float* kb0 = kb + (size_t)kt * 64 * 64;
        const float* vb0 = vb + (size_t)kt * 64 * 64;
        for (int lid = tid; lid < 64 * 16; lid += 128) {
            int m = lid >> 4, dc = (lid & 15) * 4;
            float4 v = *(const float4*)(kb0 + m * 64 + dc);
            sKtP[(dc + 0) * 68 + m] = v.x; sKtP[(dc + 1) * 68 + m] = v.y;
            sKtP[(dc + 2) * 68 + m] = v.z; sKtP[(dc + 3) * 68 + m] = v.w;
            *(float4*)(sV + m * 64 + dc) = *(const float4*)(vb0 + m * 64 + dc);
        }
        __syncthreads();

        float sc[4][8];
        #pragma unroll
        for (int i = 0; i < 4; i++)
            #pragma unroll
            for (int j = 0; j < 8; j++) sc[i][j] = 0.f;
        #pragma unroll 8
        for (int d = 0; d < 64; d++) {
            float4 qv = *(const float4*)(sQt + d * 64 + 4 * tq);
            float4 k0v = *(const float4*)(sKtP + d * 68 + 8 * tm);
            float4 k1v = *(const float4*)(sKtP + d * 68 + 8 * tm + 4);
            float kk[8] = {k0v.x, k0v.y, k0v.z, k0v.w, k1v.x, k1v.y, k1v.z, k1v.w};
            float qq[4] = {qv.x, qv.y, qv.z, qv.w};
            #pragma unroll
            for (int i = 0; i < 4; i++)
                #pragma unroll
                for (int j = 0; j < 8; j++) sc[i][j] += qq[i] * kk[j];
        }
        #pragma unroll
        for (int r = 0; r < 4; r++) {
            float mx = sc[r][0];
            #pragma unroll
            for (int j = 1; j < 8; j++) mx = fmaxf(mx, sc[r][j]);
            #pragma unroll
            for (int o = 4; o > 0; o >>= 1) mx = fmaxf(mx, __shfl_xor_sync(0xffffffffu, mx, o));
            float mn = fmaxf(mi[r], mx);
            float corr = __expf(mi[r] - mn);
            float ps = 0.f;
            #pragma unroll
            for (int j = 0; j < 8; j++) { float p = __expf(sc[r][j] - mn); sc[r][j] = p; ps += p; }
            #pragma unroll
            for (int o = 4; o > 0; o >>= 1) ps += __shfl_xor_sync(0xffffffffu, ps, o);
            li[r] = li[r] * corr + ps;
            mi[r] = mn;
            #pragma unroll
            for (int j = 0; j < 8; j++) acc[r][j] *= corr;
        }
        __syncthreads();
        #pragma unroll
        for (int r = 0; r < 4; r++)
            #pragma unroll
            for (int j = 0; j < 8; j++)
                sKtP[(8 * tm + j) * 68 + 4 * tq + r] = sc[r][j];
        __syncthreads();
        #pragma unroll 8
        for (int mm = 0; mm < 64; mm++) {
            float4 pv = *(const float4*)(sKtP + mm * 68 + 4 * tq);
            float4 v0 = *(const float4*)(sV + mm * 64 + 8 * tm);
            float4 v1 = *(const float4*)(sV + mm * 64 + 8 * tm + 4);
            float vv[8] = {v0.x, v0.y, v0.z, v0.w, v1.x, v1.y, v1.z, v1.w};
            float pp[4] = {pv.x, pv.y, pv.z, pv.w};
            #pragma unroll
            for (int i = 0; i < 4; i++)
                #pragma unroll
                for (int j = 0; j < 8; j++) acc[i][j] += pp[i] * vv[j];
        }
    }
    int b = bh >> 4, h = bh & 15;
    #pragma unroll
    for (int r = 0; r < 4; r++) {
        float inv = 1.f / li[r];
        int rowg = b * 1024 + n0 + 4 * tq + r;
        float* op = g_attn + (size_t)rowg * HIDD + h * 64 + 8 * tm;
        float4 o0 = {to_tf32(acc[r][0] * inv), to_tf32(acc[r][1] * inv),
                     to_tf32(acc[r][2] * inv), to_tf32(acc[r][3] * inv)};
        float4 o1 = {to_tf32(acc[r][4] * inv), to_tf32(acc[r][5] * inv),
                     to_tf32(acc[r][6] * inv), to_tf32(acc[r][7] * inv)};
        *(float4*)(op) = o0;
        *(float4*)(op + 4) = o1;
    }
}

// ---------------- K5: attn epilogue + residual + second x_cond ----------------
__global__ __launch_bounds__(256) void post_attn_kernel(const float* __restrict__ x,
                                                        const float* __restrict__ attn_gain) {
    int r = blockIdx.x, b = r >> 10;
    int e = threadIdx.x * 4;
    float4 y = *(const float4*)(g_tmp + (size_t)r * HIDD + e);
    __shared__ float red[32];
    float ss = y.x * y.x + y.y * y.y + y.z * y.z + y.w * y.w;
    ss = block_reduce_sum(ss, red);
    float py = rsqrtf(ss * (1.f / 1024.f) + 1e-4f) * expf(attn_gain[0]);
    float4 xv = *(const float4*)(x + (size_t)r * HIDD + e);
    float4 x1;
    x1.x = (0.7f * xv.x + 0.3f * (y.x * py)) * RSQRT058;
    x1.y = (0.7f * xv.y + 0.3f * (y.y * py)) * RSQRT058;
    x1.z = (0.7f * xv.z + 0.3f * (y.z * py)) * RSQRT058;
    x1.w = (0.7f * xv.w + 0.3f * (y.w * py)) * RSQRT058;
    *(float4*)(g_x1 + (size_t)r * HIDD + e) = x1;
    float ss1 = x1.x * x1.x + x1.y * x1.y + x1.z * x1.z + x1.w * x1.w;
    ss1 = block_reduce_sum(ss1, red);
    float p1 = rsqrtf(ss1 * (1.f / 1024.f) + 1e-4f);
    const float* gn = g_gain + b * 1024; const float* sh = g_shift + b * 1024;
    float4 o;
    o.x = to_tf32(x1.x * p1 * (1.f + gn[e + 0]) + sh[e + 0]);
    o.y = to_tf32(x1.y * p1 * (1.f + gn[e + 1]) + sh[e + 1]);
    o.z = to_tf32(x1.z * p1 * (1.f + gn[e + 2]) + sh[e + 2]);
    o.w = to_tf32(x1.w * p1 * (1.f + gn[e + 3]) + sh[e + 3]);
    *(float4*)(g_xcond + (size_t)r * HIDD + e) = o;
}

// ---------------- K6: MLP hidden activation (tf32-rounded output) ----------------
__global__ __launch_bounds__(256) void mlp_act_kernel() {
    int r = blockIdx.x;
    float* row = g_h + (size_t)r * MLPD;
    float4 v[4];
    float ss = 0.f;
    #pragma unroll
    for (int i = 0; i < 4; i++) {
        v[i] = *(const float4*)(row + (threadIdx.x + 256 * i) * 4);
        ss += v[i].x * v[i].x + v[i].y * v[i].y + v[i].z * v[i].z + v[i].w * v[i].w;
    }
    __shared__ float red[32];
    ss = block_reduce_sum(ss, red);
    float ps = rsqrtf(ss * (1.f / 4096.f) + 1e-4f);
    #pragma unroll
    for (int i = 0; i < 4; i++) {
        float u0 = v[i].x * ps, u1 = v[i].y * ps, u2 = v[i].z * ps, u3 = v[i].w * ps;
        float4 o;
        o.x = to_tf32(u0 / (1.f + expf(-u0)) * INV_0596);
        o.y = to_tf32(u1 / (1.f + expf(-u1)) * INV_0596);
        o.z = to_tf32(u2 / (1.f + expf(-u2)) * INV_0596);
        o.w = to_tf32(u3 / (1.f + expf(-u3)) * INV_0596);
        *(float4*)(row + (threadIdx.x + 256 * i) * 4) = o;
    }
}

// ---------------- K7: final epilogue ----------------
__global__ __launch_bounds__(256) void final_kernel(const float* __restrict__ mlp_gain,
                                                    float* __restrict__ out) {
    int r = blockIdx.x;
    int e = threadIdx.x * 4;
    float4 y = *(const float4*)(g_tmp + (size_t)r * HIDD + e);
    __shared__ float red[32];
    float ss = y.x * y.x + y.y * y.y + y.z * y.z + y.w * y.w;
    ss = block_reduce_sum(ss, red);
    float pm = rsqrtf(ss * (1.f / 1024.f) + 1e-4f) * expf(mlp_gain[0]);
    float4 x1 = *(const float4*)(g_x1 + (size_t)r * HIDD + e);
    float4 o;
    o.x = (0.7f * x1.x + 0.3f * (y.x * pm)) * RSQRT058;
    o.y = (0.7f * x1.y + 0.3f * (y.y * pm)) * RSQRT058;
    o.z = (0.7f * x1.z + 0.3f * (y.z * pm)) * RSQRT058;
    o.w = (0.7f * x1.w + 0.3f * (y.w * pm)) * RSQRT058;
    *(float4*)(out + (size_t)r * HIDD + e) = o;
}

// ---------------- launch ----------------
extern "C" void kernel_launch(void* const* d_in, const int* in_sizes, int n_in,
                              void* d_out, int out_size) {
    const float* x        = (const float*)d_in[0];
    const float* c        = (const float*)d_in[1];
    const float* w_cond   = (const float*)d_in[2];
    const float* w_qkv    = (const float*)d_in[3];
    const float* w_out    = (const float*)d_in[4];
    const float* w_mlp1   = (const float*)d_in[5];
    const float* w_mlp2   = (const float*)d_in[6];
    const float* attn_gain = (const float*)d_in[7];
    const float* mlp_gain  = (const float*)d_in[8];
    float* out = (float*)d_out;

    void* p;
    cudaGetSymbolAddress(&p, g_xcond);  float* xcond = (float*)p;
    cudaGetSymbolAddress(&p, g_qkv);    float* qkv   = (float*)p;
    cudaGetSymbolAddress(&p, g_attn);   float* attn  = (float*)p;
    cudaGetSymbolAddress(&p, g_h);      float* hbuf  = (float*)p;
    cudaGetSymbolAddress(&p, g_tmp);    float* tmp   = (float*)p;
    cudaGetSymbolAddress(&p, g_s_qkv);  float* sqkv  = (float*)p;
    cudaGetSymbolAddress(&p, g_s_out);  float* sout  = (float*)p;
    cudaGetSymbolAddress(&p, g_s_mlp1); float* smlp1 = (float*)p;
    cudaGetSymbolAddress(&p, g_s_mlp2); float* smlp2 = (float*)p;
    cudaGetSymbolAddress(&p, g_wtq);    float* wtq   = (float*)p;
    cudaGetSymbolAddress(&p, g_wto);    float* wto   = (float*)p;
    cudaGetSymbolAddress(&p, g_wt1);    float* wt1   = (float*)p;
    cudaGetSymbolAddress(&p, g_wt2);    float* wt2   = (float*)p;

    cudaFuncSetAttribute(attn_kernel, cudaFuncAttributeMaxDynamicSharedMemorySize,
                         ATT_SMEM_FLOATS * (int)sizeof(float));
    cudaFuncSetAttribute(gemm_mma_kernel, cudaFuncAttributeMaxDynamicSharedMemorySize,
                         GEMM_SMEM_BYTES);

    scales_kernel<<<8192, 128>>>(w_cond, w_qkv, w_out, w_mlp1, w_mlp2);
    cond_kernel<<<8, 256>>>(c, w_cond);
    transpose_scale_kernel<<<dim3(3072 / 32, 1024 / 32), 256>>>(w_qkv, sqkv, wtq, 1024, 3072);
    transpose_scale_kernel<<<dim3(1024 / 32, 1024 / 32), 256>>>(w_out, sout, wto, 1024, 1024);
    transpose_scale_kernel<<<dim3(4096 / 32, 1024 / 32), 256>>>(w_mlp1, smlp1, wt1, 1024, 4096);
    transpose_scale_kernel<<<dim3(1024 / 32, 4096 / 32), 256>>>(w_mlp2, smlp2, wt2, 4096, 1024);

    xcond_kernel<<<4096, 256>>>(x);
    gemm_mma_kernel<<<dim3(24, 32), 256, GEMM_SMEM_BYTES>>>(xcond, wtq, qkv, 4096, 3072, 1024);
    qkvnorm_kernel<<<4096, 256>>>();
    attn_kernel<<<dim3(16, 64), 128, ATT_SMEM_FLOATS * sizeof(float)>>>();
    gemm_mma_kernel<<<dim3(8, 32), 256, GEMM_SMEM_BYTES>>>(attn, wto, tmp, 4096, 1024, 1024);
    post_attn_kernel<<<4096, 256>>>(x, attn_gain);
    gemm_mma_kernel<<<dim3(32, 32), 256, GEMM_SMEM_BYTES>>>(xcond, wt1, hbuf, 4096, 4096, 1024);
    mlp_act_kernel<<<4096, 256>>>();
    gemm_mma_kernel<<<dim3(8, 32), 256, GEMM_SMEM_BYTES>>>(hbuf, wt2, tmp, 4096, 1024, 4096);
    final_kernel<<<4096, 256>>>(mlp_gain, out);
}

// round 5
// speedup vs baseline: 2.4693x; 1.3604x over previous
#include <cuda_runtime.h>
#include <math.h>
#include <stdint.h>

// ---------------- problem constants ----------------
#define BNROWS 4096
#define HIDD   1024
#define MLPD   4096

#define INV_0596 1.6778523489932886f
#define RSQRT058 1.3130643285972254f

// ---------------- scratch ----------------
__device__ float g_s_cond[1024];
__device__ float g_s_qkv[1024];
__device__ float g_s_out[1024];
__device__ float g_s_mlp1[1024];
__device__ float g_s_mlp2[4096];
__device__ float g_gain[4 * 1024];
__device__ float g_shift[4 * 1024];
__device__ float g_cpart[16][4][2048];
__device__ float g_pv[BNROWS];
__device__ float g_xcond[BNROWS * HIDD];
__device__ float g_qkv[BNROWS * 3072];
__device__ float g_q[64 * 1024 * 64];
__device__ float g_k[64 * 1024 * 64];
__device__ float g_vt[64 * 64 * 1024];          // [bh][d][n]
__device__ float g_attn[BNROWS * HIDD];
__device__ float g_x1[BNROWS * HIDD];
__device__ float g_h[(size_t)BNROWS * MLPD];
__device__ float g_tmp[BNROWS * HIDD];
__device__ float g_wtq[3072 * 1024];
__device__ float g_wto[1024 * 1024];
__device__ float g_wt1[4096 * 1024];
__device__ float g_wt2[1024 * 4096];

// ---------------- helpers ----------------
__device__ __forceinline__ float to_tf32(float x) {
    uint32_t u;
    asm("cvt.rna.tf32.f32 %0, %1;" : "=r"(u) : "f"(x));
    return __uint_as_float(u);
}

__device__ __forceinline__ float block_reduce_sum(float v, float* red) {
    __syncthreads();
    #pragma unroll
    for (int o = 16; o > 0; o >>= 1) v += __shfl_xor_sync(0xffffffffu, v, o);
    int t = threadIdx.x;
    if ((t & 31) == 0) red[t >> 5] = v;
    __syncthreads();
    if (t < 32) {
        int nw = blockDim.x >> 5;
        float r = (t < nw) ? red[t] : 0.f;
        #pragma unroll
        for (int o = 16; o > 0; o >>= 1) r += __shfl_xor_sync(0xffffffffu, r, o);
        if (t == 0) red[0] = r;
    }
    __syncthreads();
    return red[0];
}

__device__ __forceinline__ void cp16(uint32_t s, const void* g) {
    asm volatile("cp.async.cg.shared.global [%0], [%1], 16;" :: "r"(s), "l"(g));
}
__device__ __forceinline__ uint32_t smem_u32(const void* p) {
    uint32_t a;
    asm("{ .reg .u64 t; cvta.to.shared.u64 t, %1; cvt.u32.u64 %0, t; }" : "=r"(a) : "l"(p));
    return a;
}

__device__ __forceinline__ void mma_tf32(float* c, const uint32_t* a, const uint32_t* b) {
    asm volatile("mma.sync.aligned.m16n8k8.row.col.f32.tf32.tf32.f32 "
        "{%0,%1,%2,%3}, {%4,%5,%6,%7}, {%8,%9}, {%0,%1,%2,%3};"
        : "+f"(c[0]), "+f"(c[1]), "+f"(c[2]), "+f"(c[3])
        : "r"(a[0]), "r"(a[1]), "r"(a[2]), "r"(a[3]), "r"(b[0]), "r"(b[1]));
}

// ---------------- K0: weight row-norm scales ----------------
__global__ void scales_kernel(const float* __restrict__ wc, const float* __restrict__ wq,
                              const float* __restrict__ wo, const float* __restrict__ w1,
                              const float* __restrict__ w2) {
    int row = blockIdx.x;
    const float* w; int len; float inv_in; float* dst; int r;
    if (row < 1024)      { w = wc; len = 2048; inv_in = 1024.f; dst = g_s_cond; r = row; }
    else if (row < 2048) { w = wq; len = 3072; inv_in = 1024.f; dst = g_s_qkv;  r = row - 1024; }
    else if (row < 3072) { w = wo; len = 1024; inv_in = 1024.f; dst = g_s_out;  r = row - 2048; }
    else if (row < 4096) { w = w1; len = 4096; inv_in = 1024.f; dst = g_s_mlp1; r = row - 3072; }
    else                 { w = w2; len = 1024; inv_in = 4096.f; dst = g_s_mlp2; r = row - 4096; }
    const float* wr = w + (size_t)r * len;
    float ss = 0.f;
    for (int j = threadIdx.x; j < len; j += blockDim.x) { float v = wr[j]; ss += v * v; }
    __shared__ float red[32];
    ss = block_reduce_sum(ss, red);
    if (threadIdx.x == 0) {
        float norm = sqrtf(ss);
        dst[r] = 1.f / ((norm * sqrtf((float)len) + 1e-4f) * sqrtf(inv_in));
    }
}

// ---------------- transpose + scale-fold + tf32 round ----------------
__global__ __launch_bounds__(256) void transpose_scale_kernel(const float* __restrict__ W,
                                                              const float* __restrict__ s,
                                                              float* __restrict__ Wt,
                                                              int K, int N) {
    __shared__ float t[32][33];
    int k0 = blockIdx.y * 32, n0 = blockIdx.x * 32;
    int tx = threadIdx.x & 31, ty = threadIdx.x >> 5;
    #pragma unroll
    for (int i = 0; i < 32; i += 8) {
        int k = k0 + ty + i;
        t[ty + i][tx] = to_tf32(W[(size_t)k * N + n0 + tx] * s[k]);
    }
    __syncthreads();
    #pragma unroll
    for (int i = 0; i < 32; i += 8)
        Wt[(size_t)(n0 + ty + i) * K + k0 + tx] = t[tx][ty + i];
}

// ---------------- tf32 mma.sync GEMM (128x128x32) ----------------
#define GS_ROW   36
#define GS_TILE  (128 * GS_ROW)
#define GS_STAGE (2 * GS_TILE)
#define GEMM_SMEM_BYTES (2 * GS_STAGE * 4)
__global__ __launch_bounds__(256, 1)
void gemm_mma_kernel(const float* __restrict__ A, const float* __restrict__ Bt,
                     float* __restrict__ C, int M, int N, int K) {
    extern __shared__ float sm[];
    float* st[2];
    st[0] = sm;
    st[1] = sm + GS_STAGE;
    uint32_t sb[2] = {smem_u32(st[0]), smem_u32(st[1])};

    int tid = threadIdx.x;
    int wid = tid >> 5, lane = tid & 31;
    int g = lane >> 2, j = lane & 3;
    int wm = wid >> 1, wn = wid & 1;
    int bm = blockIdx.y * 128;
    int bn = blockIdx.x * 128;

    float acc[2][8][4];
    #pragma unroll
    for (int mt = 0; mt < 2; mt++)
        #pragma unroll
        for (int nt = 0; nt < 8; nt++)
            #pragma unroll
            for (int q = 0; q < 4; q++) acc[mt][nt][q] = 0.f;

    const int NC = K >> 5;

    auto load_chunk = [&](int c, int stg) {
        uint32_t sA = sb[stg];
        uint32_t sB = sb[stg] + GS_TILE * 4;
        int kc = c << 5;
        #pragma unroll
        for (int i = 0; i < 4; i++) {
            int seg = tid + 256 * i;
            int row = seg >> 3, k4 = seg & 7;
            cp16(sA + row * (GS_ROW * 4) + k4 * 16, A + (size_t)(bm + row) * K + kc + k4 * 4);
        }
        #pragma unroll
        for (int i = 0; i < 4; i++) {
            int seg = tid + 256 * i;
            int row = seg >> 3, k4 = seg & 7;
            cp16(sB + row * (GS_ROW * 4) + k4 * 16, Bt + (size_t)(bn + row) * K + kc + k4 * 4);
        }
    };

    load_chunk(0, 0);
    asm volatile("cp.async.commit_group;" ::: "memory");

    for (int c = 0; c < NC; c++) {
        int s = c & 1;
        if (c + 1 < NC) {
            load_chunk(c + 1, s ^ 1);
            asm volatile("cp.async.commit_group;" ::: "memory");
            asm volatile("cp.async.wait_group 1;" ::: "memory");
        } else {
            asm volatile("cp.async.wait_group 0;" ::: "memory");
        }
        __syncthreads();

        const uint32_t* uA = (const uint32_t*)st[s];
        const uint32_t* uB = (const uint32_t*)(st[s] + GS_TILE);
        #pragma unroll
        for (int ks = 0; ks < 4; ks++) {
            int k = ks * 8;
            uint32_t af[2][4];
            #pragma unroll
            for (int mt = 0; mt < 2; mt++) {
                int row = wm * 32 + mt * 16 + g;
                af[mt][0] = uA[row * GS_ROW + k + j];
                af[mt][1] = uA[(row + 8) * GS_ROW + k + j];
                af[mt][2] = uA[row * GS_ROW + k + j + 4];
                af[mt][3] = uA[(row + 8) * GS_ROW + k + j + 4];
            }
            #pragma unroll
            for (int nt = 0; nt < 8; nt++) {
                int n = wn * 64 + nt * 8 + g;
                uint32_t bf[2];
                bf[0] = uB[n * GS_ROW + k + j];
                bf[1] = uB[n * GS_ROW + k + j + 4];
                #pragma unroll
                for (int mt = 0; mt < 2; mt++)
                    mma_tf32(acc[mt][nt], af[mt], bf);
            }
        }
        __syncthreads();
    }

    #pragma unroll
    for (int mt = 0; mt < 2; mt++) {
        int row = bm + wm * 32 + mt * 16 + g;
        #pragma unroll
        for (int nt = 0; nt < 8; nt++) {
            int col = bn + wn * 64 + nt * 8 + 2 * j;
            float2 o0 = {acc[mt][nt][0], acc[mt][nt][1]};
            float2 o1 = {acc[mt][nt][2], acc[mt][nt][3]};
            *(float2*)(C + (size_t)row * N + col) = o0;
            *(float2*)(C + (size_t)(row + 8) * N + col) = o1;
        }
    }
}

// ---------------- K1: conditioning GEMM, split-K + reduce ----------------
__global__ __launch_bounds__(256) void cond_part_kernel(const float* __restrict__ c,
                                                        const float* __restrict__ w_cond) {
    __shared__ float ccs[4][64];
    int tid = threadIdx.x;
    int i0 = blockIdx.y * 64;
    {
        int bb = tid >> 6, ii = tid & 63;
        float v = c[bb * 1024 + i0 + ii];
        float sil = v / (1.f + expf(-v)) * INV_0596;
        ccs[bb][ii] = sil * g_s_cond[i0 + ii];
    }
    __syncthreads();
    int j = blockIdx.x * 256 + tid;
    float a0 = 0.f, a1 = 0.f, a2 = 0.f, a3 = 0.f;
    #pragma unroll 4
    for (int i = 0; i < 64; i++) {
        float w = w_cond[(size_t)(i0 + i) * 2048 + j];
        a0 += ccs[0][i] * w; a1 += ccs[1][i] * w;
        a2 += ccs[2][i] * w; a3 += ccs[3][i] * w;
    }
    g_cpart[blockIdx.y][0][j] = a0;
    g_cpart[blockIdx.y][1][j] = a1;
    g_cpart[blockIdx.y][2][j] = a2;
    g_cpart[blockIdx.y][3][j] = a3;
}

__global__ __launch_bounds__(256) void cond_reduce_kernel() {
    int idx = blockIdx.x * 256 + threadIdx.x;   // 0..8191
    int bb = idx >> 11, j = idx & 2047;
    float a = 0.f;
    #pragma unroll
    for (int s = 0; s < 16; s++) a += g_cpart[s][bb][j];
    if (j < 1024) g_gain[bb * 1024 + j] = a;
    else          g_shift[bb * 1024 + (j - 1024)] = a;
}

// ---------------- K2: x_cond ----------------
__global__ __launch_bounds__(256) void xcond_kernel(const float* __restrict__ x) {
    int r = blockIdx.x; int b = r >> 10;
    const float* xr = x + (size_t)r * HIDD;
    int e = threadIdx.x * 4;
    float4 v = *(const float4*)(xr + e);
    float ss = v.x * v.x + v.y * v.y + v.z * v.z + v.w * v.w;
    __shared__ float red[32];
    ss = block_reduce_sum(ss, red);
    float rs = rsqrtf(ss * (1.f / 1024.f) + 1e-4f);
    const float* gn = g_gain + b * 1024; const float* sh = g_shift + b * 1024;
    float4 o;
    o.x = to_tf32(v.x * rs * (1.f + gn[e + 0]) + sh[e + 0]);
    o.y = to_tf32(v.y * rs * (1.f + gn[e + 1]) + sh[e + 1]);
    o.z = to_tf32(v.z * rs * (1.f + gn[e + 2]) + sh[e + 2]);
    o.w = to_tf32(v.w * rs * (1.f + gn[e + 3]) + sh[e + 3]);
    *(float4*)(g_xcond + (size_t)r * HIDD + e) = o;
}

// ---------------- K3: q/k normalization (+v row-norm scale) ----------------
__global__ __launch_bounds__(256) void qkvnorm_kernel() {
    int r = blockIdx.x; int b = r >> 10, n = r & 1023;
    const float* row = g_qkv + (size_t)r * 3072;
    int t = threadIdx.x, e = t * 4, head = t >> 4;
    float4 q = *(const float4*)(row + e);
    float4 k = *(const float4*)(row + 1024 + e);
    float4 v = *(const float4*)(row + 2048 + e);
    __shared__ float hq[16], hk[16], hv[16];
    if (t < 16) { hq[t] = 0.f; hk[t] = 0.f; hv[t] = 0.f; }
    __syncthreads();
    float sq = q.x * q.x + q.y * q.y + q.z * q.z + q.w * q.w;
    float sk = k.x * k.x + k.y * k.y + k.z * k.z + k.w * k.w;
    float sv = v.x * v.x + v.y * v.y + v.z * v.z + v.w * v.w;
    atomicAdd(&hq[head], sq); atomicAdd(&hk[head], sk); atomicAdd(&hv[head], sv);
    __syncthreads();
    float tq = 0.f, tk = 0.f, tv = 0.f;
    #pragma unroll
    for (int h = 0; h < 16; h++) { tq += hq[h]; tk += hk[h]; tv += hv[h]; }
    float pq = rsqrtf(tq * (1.f / 1024.f) + 1e-4f);
    float pk = rsqrtf(tk * (1.f / 1024.f) + 1e-4f);
    float pv = rsqrtf(tv * (1.f / 1024.f) + 1e-4f);
    float qs = pq * rsqrtf(pq * pq * hq[head] + 1e-6f) * 0.125f;
    float ks = pk * rsqrtf(pk * pk * hk[head] + 1e-6f);
    if (t == 0) g_pv[r] = pv;
    size_t base = ((size_t)(b * 16 + head) * 1024 + n) * 64 + (e & 63);
    float4 oq = {to_tf32(q.x * qs), to_tf32(q.y * qs), to_tf32(q.z * qs), to_tf32(q.w * qs)};
    float4 ok = {to_tf32(k.x * ks), to_tf32(k.y * ks), to_tf32(k.z * ks), to_tf32(k.w * ks)};
    *(float4*)(g_q + base) = oq;
    *(float4*)(g_k + base) = ok;
}

// ---------------- V transpose: g_vt[bh][d][n] = tf32(v_norm) ----------------
__global__ __launch_bounds__(256) void vtrans_kernel() {
    __shared__ float t[32][33];
    int bh = blockIdx.z; int b = bh >> 4, h = bh & 15;
    int n0 = blockIdx.x * 32, d0 = blockIdx.y * 32;
    int tx = threadIdx.x & 31, ty = threadIdx.x >> 5;
    #pragma unroll
    for (int i = 0; i < 32; i += 8) {
        int n = n0 + ty + i;
        int rowg = b * 1024 + n;
        t[ty + i][tx] = g_qkv[(size_t)rowg * 3072 + 2048 + h * 64 + d0 + tx] * g_pv[rowg];
    }
    __syncthreads();
    #pragma unroll
    for (int i = 0; i < 32; i += 8) {
        int d = d0 + ty + i;
        g_vt[((size_t)bh * 64 + d) * 1024 + n0 + tx] = to_tf32(t[tx][ty + i]);
    }
}

// ---------------- K4: flash attention via tf32 mma.sync ----------------
// block: 64 queries, 4 warps (16 q each); K-tiles of 64.
#define AT_STR 72
#define ATT_SMEM_BYTES (4 * 64 * AT_STR * 4)
__global__ __launch_bounds__(128, 2) void attn_mma_kernel() {
    extern __shared__ float sm[];
    float* sQ  = sm;
    float* sK  = sm + 64 * AT_STR;
    float* sVt = sm + 2 * 64 * AT_STR;
    float* sP  = sm + 3 * 64 * AT_STR;
    const uint32_t* uQ  = (const uint32_t*)sQ;
    const uint32_t* uK  = (const uint32_t*)sK;
    const uint32_t* uVt = (const uint32_t*)sVt;
    const uint32_t* uP  = (const uint32_t*)sP;

    int tid = threadIdx.x;
    int w = tid >> 5, lane = tid & 31;
    int g = lane >> 2, j = lane & 3;
    int bh = blockIdx.y;
    int n0 = blockIdx.x * 64;
    const float* qb  = g_q + ((size_t)bh * 1024 + n0) * 64;
    const float* kb  = g_k + (size_t)bh * 1024 * 64;
    const float* vtb = g_vt + (size_t)bh * 64 * 1024;

    #pragma unroll
    for (int i = 0; i < 8; i++) {
        int seg = tid + 128 * i;
        int row = seg >> 4, d4 = (seg & 15) * 4;
        *(float4*)(sQ + row * AT_STR + d4) = *(const float4*)(qb + row * 64 + d4);
    }

    float accO[8][4];
    #pragma unroll
    for (int nt = 0; nt < 8; nt++)
        #pragma unroll
        for (int q = 0; q < 4; q++) accO[nt][q] = 0.f;
    float mi0 = -INFINITY, mi1 = -INFINITY, li0 = 0.f, li1 = 0.f;

    for (int kt = 0; kt < 16; kt++) {
        __syncthreads();
        const float* kb0 = kb + (size_t)kt * 64 * 64;
        #pragma unroll
        for (int i = 0; i < 8; i++) {
            int seg = tid + 128 * i;
            int row = seg >> 4, d4 = (seg & 15) * 4;
            *(float4*)(sK + row * AT_STR + d4) = *(const float4*)(kb0 + row * 64 + d4);
            *(float4*)(sVt + row * AT_STR + d4) = *(const float4*)(vtb + row * 1024 + kt * 64 + d4);
        }
        __syncthreads();

        // S = Q @ K^T  (warp rows w*16..w*16+15, all 64 keys)
        float accS[8][4];
        #pragma unroll
        for (int nt = 0; nt < 8; nt++)
            #pragma unroll
            for (int q = 0; q < 4; q++) accS[nt][q] = 0.f;
        #pragma unroll
        for (int ks = 0; ks < 8; ks++) {
            int k = ks * 8;
            uint32_t a[4];
            int r0 = (w * 16 + g) * AT_STR, r1 = (w * 16 + g + 8) * AT_STR;
            a[0] = uQ[r0 + k + j];
            a[1] = uQ[r1 + k + j];
            a[2] = uQ[r0 + k + j + 4];
            a[3] = uQ[r1 + k + j + 4];
            #pragma unroll
            for (int nt = 0; nt < 8; nt++) {
                uint32_t bfr[2];
                bfr[0] = uK[(nt * 8 + g) * AT_STR + k + j];
                bfr[1] = uK[(nt * 8 + g) * AT_STR + k + j + 4];
                mma_tf32(accS[nt], a, bfr);
            }
        }

        // online softmax: row0 = c0,c1; row1 = c2,c3
        float mx0 = -INFINITY, mx1 = -INFINITY;
        #pragma unroll
        for (int nt = 0; nt < 8; nt++) {
            mx0 = fmaxf(mx0, fmaxf(accS[nt][0], accS[nt][1]));
            mx1 = fmaxf(mx1, fmaxf(accS[nt][2], accS[nt][3]));
        }
        mx0 = fmaxf(mx0, __shfl_xor_sync(0xffffffffu, mx0, 1));
        mx0 = fmaxf(mx0, __shfl_xor_sync(0xffffffffu, mx0, 2));
        mx1 = fmaxf(mx1, __shfl_xor_sync(0xffffffffu, mx1, 1));
        mx1 = fmaxf(mx1, __shfl_xor_sync(0xffffffffu, mx1, 2));
        float nm0 = fmaxf(mi0, mx0), nm1 = fmaxf(mi1, mx1);
        float corr0 = __expf(mi0 - nm0), corr1 = __expf(mi1 - nm1);
        float ps0 = 0.f, ps1 = 0.f;
        #pragma unroll
        for (int nt = 0; nt < 8; nt++) {
            float p0 = __expf(accS[nt][0] - nm0);
            float p1 = __expf(accS[nt][1] - nm0);
            float p2 = __expf(accS[nt][2] - nm1);
            float p3 = __expf(accS[nt][3] - nm1);
            accS[nt][0] = p0; accS[nt][1] = p1; accS[nt][2] = p2; accS[nt][3] = p3;
            ps0 += p0 + p1; ps1 += p2 + p3;
        }
        ps0 += __shfl_xor_sync(0xffffffffu, ps0, 1);
        ps0 += __shfl_xor_sync(0xffffffffu, ps0, 2);
        ps1 += __shfl_xor_sync(0xffffffffu, ps1, 1);
        ps1 += __shfl_xor_sync(0xffffffffu, ps1, 2);
        li0 = li0 * corr0 + ps0; mi0 = nm0;
        li1 = li1 * corr1 + ps1; mi1 = nm1;
        #pragma unroll
        for (int nt = 0; nt < 8; nt++) {
            accO[nt][0] *= corr0; accO[nt][1] *= corr0;
            accO[nt][2] *= corr1; accO[nt][3] *= corr1;
        }

        // P -> smem (per-warp private rows)
        #pragma unroll
        for (int nt = 0; nt < 8; nt++) {
            float2 p01 = {accS[nt][0], accS[nt][1]};
            float2 p23 = {accS[nt][2], accS[nt][3]};
            *(float2*)(sP + (w * 16 + g) * AT_STR + nt * 8 + 2 * j) = p01;
            *(float2*)(sP + (w * 16 + g + 8) * AT_STR + nt * 8 + 2 * j) = p23;
        }
        __syncwarp();

        // O += P @ V  (Vt[d][m])
        #pragma unroll
        for (int ks = 0; ks < 8; ks++) {
            int k = ks * 8;
            uint32_t a[4];
            int r0 = (w * 16 + g) * AT_STR, r1 = (w * 16 + g + 8) * AT_STR;
            a[0] = uP[r0 + k + j];
            a[1] = uP[r1 + k + j];
            a[2] = uP[r0 + k + j + 4];
            a[3] = uP[r1 + k + j + 4];
            #pragma unroll
            for (int nt = 0; nt < 8; nt++) {
                uint32_t bfr[2];
                bfr[0] = uVt[(nt * 8 + g) * AT_STR + k + j];
                bfr[1] = uVt[(nt * 8 + g) * AT_STR + k + j + 4];
                mma_tf32(accO[nt], a, bfr);
            }
        }
    }

    float inv0 = 1.f / li0, inv1 = 1.f / li1;
    int b = bh >> 4, h = bh & 15;
    int row0 = b * 1024 + n0 + w * 16 + g;
    #pragma unroll
    for (int nt = 0; nt < 8; nt++) {
        int col = h * 64 + nt * 8 + 2 * j;
        float2 o0 = {to_tf32(accO[nt][0] * inv0), to_tf32(accO[nt][1] * inv0)};
        float2 o1 = {to_tf32(accO[nt][2] * inv1), to_tf32(accO[nt][3] * inv1)};
        *(float2*)(g_attn + (size_t)row0 * HIDD + col) = o0;
        *(float2*)(g_attn + (size_t)(row0 + 8) * HIDD + col) = o1;
    }
}

// ---------------- K5: attn epilogue + residual + second x_cond ----------------
__global__ __launch_bounds__(256) void post_attn_kernel(const float* __restrict__ x,
                                                        const float* __restrict__ attn_gain) {
    int r = blockIdx.x, b = r >> 10;
    int e = threadIdx.x * 4;
    float4 y = *(const float4*)(g_tmp + (size_t)r * HIDD + e);
    __shared__ float red[32];
    float ss = y.x * y.x + y.y * y.y + y.z * y.z + y.w * y.w;
    ss = block_reduce_sum(ss, red);
    float py = rsqrtf(ss * (1.f / 1024.f) + 1e-4f) * expf(attn_gain[0]);
    float4 xv = *(const float4*)(x + (size_t)r * HIDD + e);
    float4 x1;
    x1.x = (0.7f * xv.x + 0.3f * (y.x * py)) * RSQRT058;
    x1.y = (0.7f * xv.y + 0.3f * (y.y * py)) * RSQRT058;
    x1.z = (0.7f * xv.z + 0.3f * (y.z * py)) * RSQRT058;
    x1.w = (0.7f * xv.w + 0.3f * (y.w * py)) * RSQRT058;
    *(float4*)(g_x1 + (size_t)r * HIDD + e) = x1;
    float ss1 = x1.x * x1.x + x1.y * x1.y + x1.z * x1.z + x1.w * x1.w;
    ss1 = block_reduce_sum(ss1, red);
    float p1 = rsqrtf(ss1 * (1.f / 1024.f) + 1e-4f);
    const float* gn = g_gain + b * 1024; const float* sh = g_shift + b * 1024;
    float4 o;
    o.x = to_tf32(x1.x * p1 * (1.f + gn[e + 0]) + sh[e + 0]);
    o.y = to_tf32(x1.y * p1 * (1.f + gn[e + 1]) + sh[e + 1]);
    o.z = to_tf32(x1.z * p1 * (1.f + gn[e + 2]) + sh[e + 2]);
    o.w = to_tf32(x1.w * p1 * (1.f + gn[e + 3]) + sh[e + 3]);
    *(float4*)(g_xcond + (size_t)r * HIDD + e) = o;
}

// ---------------- K6: MLP hidden activation ----------------
__global__ __launch_bounds__(256) void mlp_act_kernel() {
    int r = blockIdx.x;
    float* row = g_h + (size_t)r * MLPD;
    float4 v[4];
    float ss = 0.f;
    #pragma unroll
    for (int i = 0; i < 4; i++) {
        v[i] = *(const float4*)(row + (threadIdx.x + 256 * i) * 4);
        ss += v[i].x * v[i].x + v[i].y * v[i].y + v[i].z * v[i].z + v[i].w * v[i].w;
    }
    __shared__ float red[32];
    ss = block_reduce_sum(ss, red);
    float ps = rsqrtf(ss * (1.f / 4096.f) + 1e-4f);
    #pragma unroll
    for (int i = 0; i < 4; i++) {
        float u0 = v[i].x * ps, u1 = v[i].y * ps, u2 = v[i].z * ps, u3 = v[i].w * ps;
        float4 o;
        o.x = to_tf32(u0 / (1.f + expf(-u0)) * INV_0596);
        o.y = to_tf32(u1 / (1.f + expf(-u1)) * INV_0596);
        o.z = to_tf32(u2 / (1.f + expf(-u2)) * INV_0596);
        o.w = to_tf32(u3 / (1.f + expf(-u3)) * INV_0596);
        *(float4*)(row + (threadIdx.x + 256 * i) * 4) = o;
    }
}

// ---------------- K7: final epilogue ----------------
__global__ __launch_bounds__(256) void final_kernel(const float* __restrict__ mlp_gain,
                                                    float* __restrict__ out) {
    int r = blockIdx.x;
    int e = threadIdx.x * 4;
    float4 y = *(const float4*)(g_tmp + (size_t)r * HIDD + e);
    __shared__ float red[32];
    float ss = y.x * y.x + y.y * y.y + y.z * y.z + y.w * y.w;
    ss = block_reduce_sum(ss, red);
    float pm = rsqrtf(ss * (1.f / 1024.f) + 1e-4f) * expf(mlp_gain[0]);
    float4 x1 = *(const float4*)(g_x1 + (size_t)r * HIDD + e);
    float4 o;
    o.x = (0.7f * x1.x + 0.3f * (y.x * pm)) * RSQRT058;
    o.y = (0.7f * x1.y + 0.3f * (y.y * pm)) * RSQRT058;
    o.z = (0.7f * x1.z + 0.3f * (y.z * pm)) * RSQRT058;
    o.w = (0.7f * x1.w + 0.3f * (y.w * pm)) * RSQRT058;
    *(float4*)(out + (size_t)r * HIDD + e) = o;
}

// ---------------- launch ----------------
extern "C" void kernel_launch(void* const* d_in, const int* in_sizes, int n_in,
                              void* d_out, int out_size) {
    const float* x        = (const float*)d_in[0];
    const float* c        = (const float*)d_in[1];
    const float* w_cond   = (const float*)d_in[2];
    const float* w_qkv    = (const float*)d_in[3];
    const float* w_out    = (const float*)d_in[4];
    const float* w_mlp1   = (const float*)d_in[5];
    const float* w_mlp2   = (const float*)d_in[6];
    const float* attn_gain = (const float*)d_in[7];
    const float* mlp_gain  = (const float*)d_in[8];
    float* out = (float*)d_out;

    void* p;
    cudaGetSymbolAddress(&p, g_xcond);  float* xcond = (float*)p;
    cudaGetSymbolAddress(&p, g_qkv);    float* qkv   = (float*)p;
    cudaGetSymbolAddress(&p, g_attn);   float* attn  = (float*)p;
    cudaGetSymbolAddress(&p, g_h);      float* hbuf  = (float*)p;
    cudaGetSymbolAddress(&p, g_tmp);    float* tmp   = (float*)p;
    cudaGetSymbolAddress(&p, g_s_qkv);  float* sqkv  = (float*)p;
    cudaGetSymbolAddress(&p, g_s_out);  float* sout  = (float*)p;
    cudaGetSymbolAddress(&p, g_s_mlp1); float* smlp1 = (float*)p;
    cudaGetSymbolAddress(&p, g_s_mlp2); float* smlp2 = (float*)p;
    cudaGetSymbolAddress(&p, g_wtq);    float* wtq   = (float*)p;
    cudaGetSymbolAddress(&p, g_wto);    float* wto   = (float*)p;
    cudaGetSymbolAddress(&p, g_wt1);    float* wt1   = (float*)p;
    cudaGetSymbolAddress(&p, g_wt2);    float* wt2   = (float*)p;

    cudaFuncSetAttribute(attn_mma_kernel, cudaFuncAttributeMaxDynamicSharedMemorySize,
                         ATT_SMEM_BYTES);
    cudaFuncSetAttribute(gemm_mma_kernel, cudaFuncAttributeMaxDynamicSharedMemorySize,
                         GEMM_SMEM_BYTES);

    scales_kernel<<<8192, 128>>>(w_cond, w_qkv, w_out, w_mlp1, w_mlp2);
    cond_part_kernel<<<dim3(8, 16), 256>>>(c, w_cond);
    cond_reduce_kernel<<<32, 256>>>();
    transpose_scale_kernel<<<dim3(3072 / 32, 1024 / 32), 256>>>(w_qkv, sqkv, wtq, 1024, 3072);
    transpose_scale_kernel<<<dim3(1024 / 32, 1024 / 32), 256>>>(w_out, sout, wto, 1024, 1024);
    transpose_scale_kernel<<<dim3(4096 / 32, 1024 / 32), 256>>>(w_mlp1, smlp1, wt1, 1024, 4096);
    transpose_scale_kernel<<<dim3(1024 / 32, 4096 / 32), 256>>>(w_mlp2, smlp2, wt2, 4096, 1024);

    xcond_kernel<<<4096, 256>>>(x);
    gemm_mma_kernel<<<dim3(24, 32), 256, GEMM_SMEM_BYTES>>>(xcond, wtq, qkv, 4096, 3072, 1024);
    qkvnorm_kernel<<<4096, 256>>>();
    vtrans_kernel<<<dim3(32, 2, 64), 256>>>();
    attn_mma_kernel<<<dim3(16, 64), 128, ATT_SMEM_BYTES>>>();
    gemm_mma_kernel<<<dim3(8, 32), 256, GEMM_SMEM_BYTES>>>(attn, wto, tmp, 4096, 1024, 1024);
    post_attn_kernel<<<4096, 256>>>(x, attn_gain);
    gemm_mma_kernel<<<dim3(32, 32), 256, GEMM_SMEM_BYTES>>>(xcond, wt1, hbuf, 4096, 4096, 1024);
    mlp_act_kernel<<<4096, 256>>>();
    gemm_mma_kernel<<<dim3(8, 32), 256, GEMM_SMEM_BYTES>>>(hbuf, wt2, tmp, 4096, 1024, 4096);
    final_kernel<<<4096, 256>>>(mlp_gain, out);
}

// round 7
// speedup vs baseline: 3.4530x; 1.3983x over previous
#include <cuda_runtime.h>
#include <math.h>
#include <stdint.h>

// ---------------- problem constants ----------------
#define BNROWS 4096
#define HIDD   1024
#define MLPD   4096

#define INV_0596 1.6778523489932886f
#define RSQRT058 1.3130643285972254f

// ---------------- scratch ----------------
__device__ float g_s_cond[1024];
__device__ float g_s_qkv[1024];
__device__ float g_s_out[1024];
__device__ float g_s_mlp1[1024];
__device__ float g_s_mlp2[4096];
__device__ float g_gain[4 * 1024];
__device__ float g_shift[4 * 1024];
__device__ float g_cpart[16][4][2048];
__device__ float g_pv[BNROWS];
__device__ float g_xcond[BNROWS * HIDD];
__device__ float g_qkv[BNROWS * 3072];
__device__ float g_q[64 * 1024 * 64];
__device__ float g_k[64 * 1024 * 64];
__device__ float g_vt[64 * 64 * 1024];          // [bh][d][n]
__device__ float g_attn[BNROWS * HIDD];
__device__ float g_x1[BNROWS * HIDD];
__device__ float g_h[(size_t)BNROWS * MLPD];
__device__ float g_tmp[BNROWS * HIDD];
__device__ float g_wtq[3072 * 1024];
__device__ float g_wto[1024 * 1024];
__device__ float g_wt1[4096 * 1024];
__device__ float g_wt2[1024 * 4096];

// ---------------- helpers ----------------
__device__ __forceinline__ float to_tf32(float x) {
    uint32_t u;
    asm("cvt.rna.tf32.f32 %0, %1;" : "=r"(u) : "f"(x));
    return __uint_as_float(u);
}

__device__ __forceinline__ float block_reduce_sum(float v, float* red) {
    __syncthreads();
    #pragma unroll
    for (int o = 16; o > 0; o >>= 1) v += __shfl_xor_sync(0xffffffffu, v, o);
    int t = threadIdx.x;
    if ((t & 31) == 0) red[t >> 5] = v;
    __syncthreads();
    if (t < 32) {
        int nw = blockDim.x >> 5;
        float r = (t < nw) ? red[t] : 0.f;
        #pragma unroll
        for (int o = 16; o > 0; o >>= 1) r += __shfl_xor_sync(0xffffffffu, r, o);
        if (t == 0) red[0] = r;
    }
    __syncthreads();
    return red[0];
}

__device__ __forceinline__ void cp16(uint32_t s, const void* g) {
    asm volatile("cp.async.cg.shared.global [%0], [%1], 16;" :: "r"(s), "l"(g));
}
__device__ __forceinline__ uint32_t smem_u32(const void* p) {
    uint32_t a;
    asm("{ .reg .u64 t; cvta.to.shared.u64 t, %1; cvt.u32.u64 %0, t; }" : "=r"(a) : "l"(p));
    return a;
}

__device__ __forceinline__ void mma_tf32(float* c, const uint32_t* a, const uint32_t* b) {
    asm volatile("mma.sync.aligned.m16n8k8.row.col.f32.tf32.tf32.f32 "
        "{%0,%1,%2,%3}, {%4,%5,%6,%7}, {%8,%9}, {%0,%1,%2,%3};"
        : "+f"(c[0]), "+f"(c[1]), "+f"(c[2]), "+f"(c[3])
        : "r"(a[0]), "r"(a[1]), "r"(a[2]), "r"(a[3]), "r"(b[0]), "r"(b[1]));
}

// ---------------- K0: weight row-norm scales ----------------
__global__ void scales_kernel(const float* __restrict__ wc, const float* __restrict__ wq,
                              const float* __restrict__ wo, const float* __restrict__ w1,
                              const float* __restrict__ w2) {
    int row = blockIdx.x;
    const float* w; int len; float inv_in; float* dst; int r;
    if (row < 1024)      { w = wc; len = 2048; inv_in = 1024.f; dst = g_s_cond; r = row; }
    else if (row < 2048) { w = wq; len = 3072; inv_in = 1024.f; dst = g_s_qkv;  r = row - 1024; }
    else if (row < 3072) { w = wo; len = 1024; inv_in = 1024.f; dst = g_s_out;  r = row - 2048; }
    else if (row < 4096) { w = w1; len = 4096; inv_in = 1024.f; dst = g_s_mlp1; r = row - 3072; }
    else                 { w = w2; len = 1024; inv_in = 4096.f; dst = g_s_mlp2; r = row - 4096; }
    const float* wr = w + (size_t)r * len;
    float ss = 0.f;
    for (int j = threadIdx.x; j < len; j += blockDim.x) { float v = wr[j]; ss += v * v; }
    __shared__ float red[32];
    ss = block_reduce_sum(ss, red);
    if (threadIdx.x == 0) {
        float norm = sqrtf(ss);
        dst[r] = 1.f / ((norm * sqrtf((float)len) + 1e-4f) * sqrtf(inv_in));
    }
}

// ---------------- transpose + scale-fold + tf32 round ----------------
__global__ __launch_bounds__(256) void transpose_scale_kernel(const float* __restrict__ W,
                                                              const float* __restrict__ s,
                                                              float* __restrict__ Wt,
                                                              int K, int N) {
    __shared__ float t[32][33];
    int k0 = blockIdx.y * 32, n0 = blockIdx.x * 32;
    int tx = threadIdx.x & 31, ty = threadIdx.x >> 5;
    #pragma unroll
    for (int i = 0; i < 32; i += 8) {
        int k = k0 + ty + i;
        t[ty + i][tx] = to_tf32(W[(size_t)k * N + n0 + tx] * s[k]);
    }
    __syncthreads();
    #pragma unroll
    for (int i = 0; i < 32; i += 8)
        Wt[(size_t)(n0 + ty + i) * K + k0 + tx] = t[tx][ty + i];
}

// ---------------- tf32 mma.sync GEMM: 128x256x32, 3-stage, warp tile 64x64 ----------------
#define SROW        36
#define SA_FLOATS   (128 * SROW)
#define SB_FLOATS   (256 * SROW)
#define STG_FLOATS  (SA_FLOATS + SB_FLOATS)
#define GEMM_SMEM_BYTES (3 * STG_FLOATS * 4)
__global__ __launch_bounds__(256, 1)
void gemm_mma_kernel(const float* __restrict__ A, const float* __restrict__ Bt,
                     float* __restrict__ C, int M, int N, int K) {
    extern __shared__ float sm[];
    int tid = threadIdx.x;
    int wid = tid >> 5, lane = tid & 31;
    int g = lane >> 2, j = lane & 3;
    int wm = wid >> 2, wn = wid & 3;      // 2 x 4 warps, warp tile 64x64
    int bm = blockIdx.y * 128;
    int bn = blockIdx.x * 256;
    uint32_t sb = smem_u32(sm);

    float acc[4][8][4];
    #pragma unroll
    for (int mt = 0; mt < 4; mt++)
        #pragma unroll
        for (int nt = 0; nt < 8; nt++)
            #pragma unroll
            for (int q = 0; q < 4; q++) acc[mt][nt][q] = 0.f;

    const int NC = K >> 5;

    auto load_chunk = [&](int c, int stg) {
        uint32_t sA = sb + stg * (STG_FLOATS * 4);
        uint32_t sB = sA + SA_FLOATS * 4;
        int kc = c << 5;
        #pragma unroll
        for (int i = 0; i < 4; i++) {               // A: 1024 cp16
            int seg = tid + 256 * i;
            int row = seg >> 3, k4 = seg & 7;
            cp16(sA + row * (SROW * 4) + k4 * 16, A + (size_t)(bm + row) * K + kc + k4 * 4);
        }
        #pragma unroll
        for (int i = 0; i < 8; i++) {               // B: 2048 cp16
            int seg = tid + 256 * i;
            int row = seg >> 3, k4 = seg & 7;
            cp16(sB + row * (SROW * 4) + k4 * 16, Bt + (size_t)(bn + row) * K + kc + k4 * 4);
        }
    };

    load_chunk(0, 0);
    asm volatile("cp.async.commit_group;" ::: "memory");
    load_chunk(1, 1);
    asm volatile("cp.async.commit_group;" ::: "memory");

    for (int c = 0; c < NC; c++) {
        if (c < NC - 1) asm volatile("cp.async.wait_group 1;" ::: "memory");
        else            asm volatile("cp.async.wait_group 0;" ::: "memory");
        __syncthreads();

        int stg = c % 3;
        const uint32_t* uA = (const uint32_t*)(sm + stg * STG_FLOATS);
        const uint32_t* uB = (const uint32_t*)(sm + stg * STG_FLOATS + SA_FLOATS);
        #pragma unroll
        for (int ks = 0; ks < 4; ks++) {
            int k = ks * 8;
            uint32_t af[4][4];
            #pragma unroll
            for (int mt = 0; mt < 4; mt++) {
                int row = wm * 64 + mt * 16 + g;
                af[mt][0] = uA[row * SROW + k + j];
                af[mt][1] = uA[(row + 8) * SROW + k + j];
                af[mt][2] = uA[row * SROW + k + j + 4];
                af[mt][3] = uA[(row + 8) * SROW + k + j + 4];
            }
            #pragma unroll
            for (int nt = 0; nt < 8; nt++) {
                int n = wn * 64 + nt * 8 + g;
                uint32_t bfr[2];
                bfr[0] = uB[n * SROW + k + j];
                bfr[1] = uB[n * SROW + k + j + 4];
                #pragma unroll
                for (int mt = 0; mt < 4; mt++)
                    mma_tf32(acc[mt][nt], af[mt], bfr);
            }
        }

        if (c + 2 < NC) {
            load_chunk(c + 2, (c + 2) % 3);
            asm volatile("cp.async.commit_group;" ::: "memory");
        }
    }

    #pragma unroll
    for (int mt = 0; mt < 4; mt++) {
        int row = bm + wm * 64 + mt * 16 + g;
        #pragma unroll
        for (int nt = 0; nt < 8; nt++) {
            int col = bn + wn * 64 + nt * 8 + 2 * j;
            float2 o0 = {acc[mt][nt][0], acc[mt][nt][1]};
            float2 o1 = {acc[mt][nt][2], acc[mt][nt][3]};
            *(float2*)(C + (size_t)row * N + col) = o0;
            *(float2*)(C + (size_t)(row + 8) * N + col) = o1;
        }
    }
}

// ---------------- K1: conditioning GEMM, split-K + reduce ----------------
__global__ __launch_bounds__(256) void cond_part_kernel(const float* __restrict__ c,
                                                        const float* __restrict__ w_cond) {
    __shared__ float ccs[4][64];
    int tid = threadIdx.x;
    int i0 = blockIdx.y * 64;
    {
        int bb = tid >> 6, ii = tid & 63;
        float v = c[bb * 1024 + i0 + ii];
        float sil = v / (1.f + expf(-v)) * INV_0596;
        ccs[bb][ii] = sil * g_s_cond[i0 + ii];
    }
    __syncthreads();
    int j = blockIdx.x * 256 + tid;
    float a0 = 0.f, a1 = 0.f, a2 = 0.f, a3 = 0.f;
    #pragma unroll 4
    for (int i = 0; i < 64; i++) {
        float w = w_cond[(size_t)(i0 + i) * 2048 + j];
        a0 += ccs[0][i] * w; a1 += ccs[1][i] * w;
        a2 += ccs[2][i] * w; a3 += ccs[3][i] * w;
    }
    g_cpart[blockIdx.y][0][j] = a0;
    g_cpart[blockIdx.y][1][j] = a1;
    g_cpart[blockIdx.y][2][j] = a2;
    g_cpart[blockIdx.y][3][j] = a3;
}

__global__ __launch_bounds__(256) void cond_reduce_kernel() {
    int idx = blockIdx.x * 256 + threadIdx.x;
    int bb = idx >> 11, j = idx & 2047;
    float a = 0.f;
    #pragma unroll
    for (int s = 0; s < 16; s++) a += g_cpart[s][bb][j];
    if (j < 1024) g_gain[bb * 1024 + j] = a;
    else          g_shift[bb * 1024 + (j - 1024)] = a;
}

// ---------------- K2: x_cond ----------------
__global__ __launch_bounds__(256) void xcond_kernel(const float* __restrict__ x) {
    int r = blockIdx.x; int b = r >> 10;
    const float* xr = x + (size_t)r * HIDD;
    int e = threadIdx.x * 4;
    float4 v = *(const float4*)(xr + e);
    float ss = v.x * v.x + v.y * v.y + v.z * v.z + v.w * v.w;
    __shared__ float red[32];
    ss = block_reduce_sum(ss, red);
    float rs = rsqrtf(ss * (1.f / 1024.f) + 1e-4f);
    const float* gn = g_gain + b * 1024; const float* sh = g_shift + b * 1024;
    float4 o;
    o.x = to_tf32(v.x * rs * (1.f + gn[e + 0]) + sh[e + 0]);
    o.y = to_tf32(v.y * rs * (1.f + gn[e + 1]) + sh[e + 1]);
    o.z = to_tf32(v.z * rs * (1.f + gn[e + 2]) + sh[e + 2]);
    o.w = to_tf32(v.w * rs * (1.f + gn[e + 3]) + sh[e + 3]);
    *(float4*)(g_xcond + (size_t)r * HIDD + e) = o;
}

// ---------------- K3: q/k normalization (+v row-norm scale) ----------------
__global__ __launch_bounds__(256) void qkvnorm_kernel() {
    int r = blockIdx.x; int b = r >> 10, n = r & 1023;
    const float* row = g_qkv + (size_t)r * 3072;
    int t = threadIdx.x, e = t * 4, head = t >> 4;
    float4 q = *(const float4*)(row + e);
    float4 k = *(const float4*)(row + 1024 + e);
    float4 v = *(const float4*)(row + 2048 + e);
    __shared__ float hq[16], hk[16], hv[16];
    if (t < 16) { hq[t] = 0.f; hk[t] = 0.f; hv[t] = 0.f; }
    __syncthreads();
    float sq = q.x * q.x + q.y * q.y + q.z * q.z + q.w * q.w;
    float sk = k.x * k.x + k.y * k.y + k.z * k.z + k.w * k.w;
    float sv = v.x * v.x + v.y * v.y + v.z * v.z + v.w * v.w;
    atomicAdd(&hq[head], sq); atomicAdd(&hk[head], sk); atomicAdd(&hv[head], sv);
    __syncthreads();
    float tq = 0.f, tk = 0.f, tv = 0.f;
    #pragma unroll
    for (int h = 0; h < 16; h++) { tq += hq[h]; tk += hk[h]; tv += hv[h]; }
    float pq = rsqrtf(tq * (1.f / 1024.f) + 1e-4f);
    float pk = rsqrtf(tk * (1.f / 1024.f) + 1e-4f);
    float pv = rsqrtf(tv * (1.f / 1024.f) + 1e-4f);
    float qs = pq * rsqrtf(pq * pq * hq[head] + 1e-6f) * 0.125f;
    float ks = pk * rsqrtf(pk * pk * hk[head] + 1e-6f);
    if (t == 0) g_pv[r] = pv;
    size_t base = ((size_t)(b * 16 + head) * 1024 + n) * 64 + (e & 63);
    float4 oq = {to_tf32(q.x * qs), to_tf32(q.y * qs), to_tf32(q.z * qs), to_tf32(q.w * qs)};
    float4 ok = {to_tf32(k.x * ks), to_tf32(k.y * ks), to_tf32(k.z * ks), to_tf32(k.w * ks)};
    *(float4*)(g_q + base) = oq;
    *(float4*)(g_k + base) = ok;
}

// ---------------- V transpose ----------------
__global__ __launch_bounds__(256) void vtrans_kernel() {
    __shared__ float t[32][33];
    int bh = blockIdx.z; int b = bh >> 4, h = bh & 15;
    int n0 = blockIdx.x * 32, d0 = blockIdx.y * 32;
    int tx = threadIdx.x & 31, ty = threadIdx.x >> 5;
    #pragma unroll
    for (int i = 0; i < 32; i += 8) {
        int n = n0 + ty + i;
        int rowg = b * 1024 + n;
        t[ty + i][tx] = g_qkv[(size_t)rowg * 3072 + 2048 + h * 64 + d0 + tx] * g_pv[rowg];
    }
    __syncthreads();
    #pragma unroll
    for (int i = 0; i < 32; i += 8) {
        int d = d0 + ty + i;
        g_vt[((size_t)bh * 64 + d) * 1024 + n0 + tx] = to_tf32(t[tx][ty + i]);
    }
}

// ---------------- K4: flash attention via tf32 mma.sync ----------------
#define AT_STR 72
#define ATT_SMEM_BYTES (4 * 64 * AT_STR * 4)
__global__ __launch_bounds__(128, 2) void attn_mma_kernel() {
    extern __shared__ float sm[];
    float* sQ  = sm;
    float* sK  = sm + 64 * AT_STR;
    float* sVt = sm + 2 * 64 * AT_STR;
    float* sP  = sm + 3 * 64 * AT_STR;
    const uint32_t* uQ  = (const uint32_t*)sQ;
    const uint32_t* uK  = (const uint32_t*)sK;
    const uint32_t* uVt = (const uint32_t*)sVt;
    const uint32_t* uP  = (const uint32_t*)sP;

    int tid = threadIdx.x;
    int w = tid >> 5, lane = tid & 31;
    int g = lane >> 2, j = lane & 3;
    int bh = blockIdx.y;
    int n0 = blockIdx.x * 64;
    const float* qb  = g_q + ((size_t)bh * 1024 + n0) * 64;
    const float* kb  = g_k + (size_t)bh * 1024 * 64;
    const float* vtb = g_vt + (size_t)bh * 64 * 1024;

    #pragma unroll
    for (int i = 0; i < 8; i++) {
        int seg = tid + 128 * i;
        int row = seg >> 4, d4 = (seg & 15) * 4;
        *(float4*)(sQ + row * AT_STR + d4) = *(const float4*)(qb + row * 64 + d4);
    }

    float accO[8][4];
    #pragma unroll
    for (int nt = 0; nt < 8; nt++)
        #pragma unroll
        for (int q = 0; q < 4; q++) accO[nt][q] = 0.f;
    float mi0 = -INFINITY, mi1 = -INFINITY, li0 = 0.f, li1 = 0.f;

    for (int kt = 0; kt < 16; kt++) {
        __syncthreads();
        const float* kb0 = kb + (size_t)kt * 64 * 64;
        #pragma unroll
        for (int i = 0; i < 8; i++) {
            int seg = tid + 128 * i;
            int row = seg >> 4, d4 = (seg & 15) * 4;
            *(float4*)(sK + row * AT_STR + d4) = *(const float4*)(kb0 + row * 64 + d4);
            *(float4*)(sVt + row * AT_STR + d4) = *(const float4*)(vtb + row * 1024 + kt * 64 + d4);
        }
        __syncthreads();

        float accS[8][4];
        #pragma unroll
        for (int nt = 0; nt < 8; nt++)
            #pragma unroll
            for (int q = 0; q < 4; q++) accS[nt][q] = 0.f;
        #pragma unroll
        for (int ks = 0; ks < 8; ks++) {
            int k = ks * 8;
            uint32_t a[4];
            int r0 = (w * 16 + g) * AT_STR, r1 = (w * 16 + g + 8) * AT_STR;
            a[0] = uQ[r0 + k + j];
            a[1] = uQ[r1 + k + j];
            a[2] = uQ[r0 + k + j + 4];
            a[3] = uQ[r1 + k + j + 4];
            #pragma unroll
            for (int nt = 0; nt < 8; nt++) {
                uint32_t bfr[2];
                bfr[0] = uK[(nt * 8 + g) * AT_STR + k + j];
                bfr[1] = uK[(nt * 8 + g) * AT_STR + k + j + 4];
                mma_tf32(accS[nt], a, bfr);
            }
        }

        float mx0 = -INFINITY, mx1 = -INFINITY;
        #pragma unroll
        for (int nt = 0; nt < 8; nt++) {
            mx0 = fmaxf(mx0, fmaxf(accS[nt][0], accS[nt][1]));
            mx1 = fmaxf(mx1, fmaxf(accS[nt][2], accS[nt][3]));
        }
        mx0 = fmaxf(mx0, __shfl_xor_sync(0xffffffffu, mx0, 1));
        mx0 = fmaxf(mx0, __shfl_xor_sync(0xffffffffu, mx0, 2));
        mx1 = fmaxf(mx1, __shfl_xor_sync(0xffffffffu, mx1, 1));
        mx1 = fmaxf(mx1, __shfl_xor_sync(0xffffffffu, mx1, 2));
        float nm0 = fmaxf(mi0, mx0), nm1 = fmaxf(mi1, mx1);
        float corr0 = __expf(mi0 - nm0), corr1 = __expf(mi1 - nm1);
        float ps0 = 0.f, ps1 = 0.f;
        #pragma unroll
        for (int nt = 0; nt < 8; nt++) {
            float p0 = __expf(accS[nt][0] - nm0);
            float p1 = __expf(accS[nt][1] - nm0);
            float p2 = __expf(accS[nt][2] - nm1);
            float p3 = __expf(accS[nt][3] - nm1);
            accS[nt][0] = p0; accS[nt][1] = p1; accS[nt][2] = p2; accS[nt][3] = p3;
            ps0 += p0 + p1; ps1 += p2 + p3;
        }
        ps0 += __shfl_xor_sync(0xffffffffu, ps0, 1);
        ps0 += __shfl_xor_sync(0xffffffffu, ps0, 2);
        ps1 += __shfl_xor_sync(0xffffffffu, ps1, 1);
        ps1 += __shfl_xor_sync(0xffffffffu, ps1, 2);
        li0 = li0 * corr0 + ps0; mi0 = nm0;
        li1 = li1 * corr1 + ps1; mi1 = nm1;
        #pragma unroll
        for (int nt = 0; nt < 8; nt++) {
            accO[nt][0] *= corr0; accO[nt][1] *= corr0;
            accO[nt][2] *= corr1; accO[nt][3] *= corr1;
        }

        #pragma unroll
        for (int nt = 0; nt < 8; nt++) {
            float2 p01 = {accS[nt][0], accS[nt][1]};
            float2 p23 = {accS[nt][2], accS[nt][3]};
            *(float2*)(sP + (w * 16 + g) * AT_STR + nt * 8 + 2 * j) = p01;
            *(float2*)(sP + (w * 16 + g + 8) * AT_STR + nt * 8 + 2 * j) = p23;
        }
        __syncwarp();

        #pragma unroll
        for (int ks = 0; ks < 8; ks++) {
            int k = ks * 8;
            uint32_t a[4];
            int r0 = (w * 16 + g) * AT_STR, r1 = (w * 16 + g + 8) * AT_STR;
            a[0] = uP[r0 + k + j];
            a[1] = uP[r1 + k + j];
            a[2] = uP[r0 + k + j + 4];
            a[3] = uP[r1 + k + j + 4];
            #pragma unroll
            for (int nt = 0; nt < 8; nt++) {
                uint32_t bfr[2];
                bfr[0] = uVt[(nt * 8 + g) * AT_STR + k + j];
                bfr[1] = uVt[(nt * 8 + g) * AT_STR + k + j + 4];
                mma_tf32(accO[nt], a, bfr);
            }
        }
    }

    float inv0 = 1.f / li0, inv1 = 1.f / li1;
    int b = bh >> 4, h = bh & 15;
    int row0 = b * 1024 + n0 + w * 16 + g;
    #pragma unroll
    for (int nt = 0; nt < 8; nt++) {
        int col = h * 64 + nt * 8 + 2 * j;
        float2 o0 = {to_tf32(accO[nt][0] * inv0), to_tf32(accO[nt][1] * inv0)};
        float2 o1 = {to_tf32(accO[nt][2] * inv1), to_tf32(accO[nt][3] * inv1)};
        *(float2*)(g_attn + (size_t)row0 * HIDD + col) = o0;
        *(float2*)(g_attn + (size_t)(row0 + 8) * HIDD + col) = o1;
    }
}

// ---------------- K5: attn epilogue + residual + second x_cond ----------------
__global__ __launch_bounds__(256) void post_attn_kernel(const float* __restrict__ x,
                                                        const float* __restrict__ attn_gain) {
    int r = blockIdx.x, b = r >> 10;
    int e = threadIdx.x * 4;
    float4 y = *(const float4*)(g_tmp + (size_t)r * HIDD + e);
    __shared__ float red[32];
    float ss = y.x * y.x + y.y * y.y + y.z * y.z + y.w * y.w;
    ss = block_reduce_sum(ss, red);
    float py = rsqrtf(ss * (1.f / 1024.f) + 1e-4f) * expf(attn_gain[0]);
    float4 xv = *(const float4*)(x + (size_t)r * HIDD + e);
    float4 x1;
    x1.x = (0.7f * xv.x + 0.3f * (y.x * py)) * RSQRT058;
    x1.y = (0.7f * xv.y + 0.3f * (y.y * py)) * RSQRT058;
    x1.z = (0.7f * xv.z + 0.3f * (y.z * py)) * RSQRT058;
    x1.w = (0.7f * xv.w + 0.3f * (y.w * py)) * RSQRT058;
    *(float4*)(g_x1 + (size_t)r * HIDD + e) = x1;
    float ss1 = x1.x * x1.x + x1.y * x1.y + x1.z * x1.z + x1.w * x1.w;
    ss1 = block_reduce_sum(ss1, red);
    float p1 = rsqrtf(ss1 * (1.f / 1024.f) + 1e-4f);
    const float* gn = g_gain + b * 1024; const float* sh = g_shift + b * 1024;
    float4 o;
    o.x = to_tf32(x1.x * p1 * (1.f + gn[e + 0]) + sh[e + 0]);
    o.y = to_tf32(x1.y * p1 * (1.f + gn[e + 1]) + sh[e + 1]);
    o.z = to_tf32(x1.z * p1 * (1.f + gn[e + 2]) + sh[e + 2]);
    o.w = to_tf32(x1.w * p1 * (1.f + gn[e + 3]) + sh[e + 3]);
    *(float4*)(g_xcond + (size_t)r * HIDD + e) = o;
}

// ---------------- K6: MLP hidden activation ----------------
__global__ __launch_bounds__(256) void mlp_act_kernel() {
    int r = blockIdx.x;
    float* row = g_h + (size_t)r * MLPD;
    float4 v[4];
    float ss = 0.f;
    #pragma unroll
    for (int i = 0; i < 4; i++) {
        v[i] = *(const float4*)(row + (threadIdx.x + 256 * i) * 4);
        ss += v[i].x * v[i].x + v[i].y * v[i].y + v[i].z * v[i].z + v[i].w * v[i].w;
    }
    __shared__ float red[32];
    ss = block_reduce_sum(ss, red);
    float ps = rsqrtf(ss * (1.f / 4096.f) + 1e-4f);
    #pragma unroll
    for (int i = 0; i < 4; i++) {
        float u0 = v[i].x * ps, u1 = v[i].y * ps, u2 = v[i].z * ps, u3 = v[i].w * ps;
        float4 o;
        o.x = to_tf32(u0 / (1.f + expf(-u0)) * INV_0596);
        o.y = to_tf32(u1 / (1.f + expf(-u1)) * INV_0596);
        o.z = to_tf32(u2 / (1.f + expf(-u2)) * INV_0596);
        o.w = to_tf32(u3 / (1.f + expf(-u3)) * INV_0596);
        *(float4*)(row + (threadIdx.x + 256 * i) * 4) = o;
    }
}

// ---------------- K7: final epilogue ----------------
__global__ __launch_bounds__(256) void final_kernel(const float* __restrict__ mlp_gain,
                                                    float* __restrict__ out) {
    int r = blockIdx.x;
    int e = threadIdx.x * 4;
    float4 y = *(const float4*)(g_tmp + (size_t)r * HIDD + e);
    __shared__ float red[32];
    float ss = y.x * y.x + y.y * y.y + y.z * y.z + y.w * y.w;
    ss = block_reduce_sum(ss, red);
    float pm = rsqrtf(ss * (1.f / 1024.f) + 1e-4f) * expf(mlp_gain[0]);
    float4 x1 = *(const float4*)(g_x1 + (size_t)r * HIDD + e);
    float4 o;
    o.x = (0.7f * x1.x + 0.3f * (y.x * pm)) * RSQRT058;
    o.y = (0.7f * x1.y + 0.3f * (y.y * pm)) * RSQRT058;
    o.z = (0.7f * x1.z + 0.3f * (y.z * pm)) * RSQRT058;
    o.w = (0.7f * x1.w + 0.3f * (y.w * pm)) * RSQRT058;
    *(float4*)(out + (size_t)r * HIDD + e) = o;
}

// ---------------- launch ----------------
extern "C" void kernel_launch(void* const* d_in, const int* in_sizes, int n_in,
                              void* d_out, int out_size) {
    const float* x        = (const float*)d_in[0];
    const float* c        = (const float*)d_in[1];
    const float* w_cond   = (const float*)d_in[2];
    const float* w_qkv    = (const float*)d_in[3];
    const float* w_out    = (const float*)d_in[4];
    const float* w_mlp1   = (const float*)d_in[5];
    const float* w_mlp2   = (const float*)d_in[6];
    const float* attn_gain = (const float*)d_in[7];
    const float* mlp_gain  = (const float*)d_in[8];
    float* out = (float*)d_out;

    void* p;
    cudaGetSymbolAddress(&p, g_xcond);  float* xcond = (float*)p;
    cudaGetSymbolAddress(&p, g_qkv);    float* qkv   = (float*)p;
    cudaGetSymbolAddress(&p, g_attn);   float* attn  = (float*)p;
    cudaGetSymbolAddress(&p, g_h);      float* hbuf  = (float*)p;
    cudaGetSymbolAddress(&p, g_tmp);    float* tmp   = (float*)p;
    cudaGetSymbolAddress(&p, g_s_qkv);  float* sqkv  = (float*)p;
    cudaGetSymbolAddress(&p, g_s_out);  float* sout  = (float*)p;
    cudaGetSymbolAddress(&p, g_s_mlp1); float* smlp1 = (float*)p;
    cudaGetSymbolAddress(&p, g_s_mlp2); float* smlp2 = (float*)p;
    cudaGetSymbolAddress(&p, g_wtq);    float* wtq   = (float*)p;
    cudaGetSymbolAddress(&p, g_wto);    float* wto   = (float*)p;
    cudaGetSymbolAddress(&p, g_wt1);    float* wt1   = (float*)p;
    cudaGetSymbolAddress(&p, g_wt2);    float* wt2   = (float*)p;

    cudaFuncSetAttribute(attn_mma_kernel, cudaFuncAttributeMaxDynamicSharedMemorySize,
                         ATT_SMEM_BYTES);
    cudaFuncSetAttribute(gemm_mma_kernel, cudaFuncAttributeMaxDynamicSharedMemorySize,
                         GEMM_SMEM_BYTES);

    scales_kernel<<<8192, 128>>>(w_cond, w_qkv, w_out, w_mlp1, w_mlp2);
    cond_part_kernel<<<dim3(8, 16), 256>>>(c, w_cond);
    cond_reduce_kernel<<<32, 256>>>();
    transpose_scale_kernel<<<dim3(3072 / 32, 1024 / 32), 256>>>(w_qkv, sqkv, wtq, 1024, 3072);
    transpose_scale_kernel<<<dim3(1024 / 32, 1024 / 32), 256>>>(w_out, sout, wto, 1024, 1024);
    transpose_scale_kernel<<<dim3(4096 / 32, 1024 / 32), 256>>>(w_mlp1, smlp1, wt1, 1024, 4096);
    transpose_scale_kernel<<<dim3(1024 / 32, 4096 / 32), 256>>>(w_mlp2, smlp2, wt2, 4096, 1024);

    xcond_kernel<<<4096, 256>>>(x);
    gemm_mma_kernel<<<dim3(12, 32), 256, GEMM_SMEM_BYTES>>>(xcond, wtq, qkv, 4096, 3072, 1024);
    qkvnorm_kernel<<<4096, 256>>>();
    vtrans_kernel<<<dim3(32, 2, 64), 256>>>();
    attn_mma_kernel<<<dim3(16, 64), 128, ATT_SMEM_BYTES>>>();
    gemm_mma_kernel<<<dim3(4, 32), 256, GEMM_SMEM_BYTES>>>(attn, wto, tmp, 4096, 1024, 1024);
    post_attn_kernel<<<4096, 256>>>(x, attn_gain);
    gemm_mma_kernel<<<dim3(16, 32), 256, GEMM_SMEM_BYTES>>>(xcond, wt1, hbuf, 4096, 4096, 1024);
    mlp_act_kernel<<<4096, 256>>>();
    gemm_mma_kernel<<<dim3(4, 32), 256, GEMM_SMEM_BYTES>>>(hbuf, wt2, tmp, 4096, 1024, 4096);
    final_kernel<<<4096, 256>>>(mlp_gain, out);
}

// round 8
// speedup vs baseline: 5.9355x; 1.7189x over previous
#include <cuda_runtime.h>
#include <cuda_fp16.h>
#include <math.h>
#include <stdint.h>

// ---------------- problem constants ----------------
#define BNROWS 4096
#define HIDD   1024
#define MLPD   4096

#define INV_0596 1.6778523489932886f
#define RSQRT058 1.3130643285972254f
#define WSCALE   4096.0f
#define INV_WS   (1.0f / 4096.0f)

// ---------------- scratch ----------------
__device__ float g_s_cond[1024];
__device__ float g_s_qkv[1024];
__device__ float g_s_out[1024];
__device__ float g_s_mlp1[1024];
__device__ float g_s_mlp2[4096];
__device__ float g_gain[4 * 1024];
__device__ float g_shift[4 * 1024];
__device__ float g_cpart[16][4][2048];
__device__ float g_pv[BNROWS];                    // pv * INV_WS
__device__ float g_qkv[BNROWS * 3072];            // GEMM out (x4096)
__device__ float g_x1[BNROWS * HIDD];
__device__ float g_h[(size_t)BNROWS * MLPD];      // GEMM out (x4096)
__device__ float g_tmp[BNROWS * HIDD];            // GEMM out (x4096)
// fp16 operand buffers
__device__ __half g_xcondh[BNROWS * HIDD];
__device__ __half g_attnh[BNROWS * HIDD];
__device__ __half g_hh[(size_t)BNROWS * MLPD];
__device__ __half g_qh[64 * 1024 * 64];
__device__ __half g_kh[64 * 1024 * 64];
__device__ __half g_vth[64 * 64 * 1024];          // [bh][d][n]
// transposed + scaled (x4096) fp16 weights [N][K]
__device__ __half g_wtq[3072 * 1024];
__device__ __half g_wto[1024 * 1024];
__device__ __half g_wt1[4096 * 1024];
__device__ __half g_wt2[1024 * 4096];

// ---------------- helpers ----------------
__device__ __forceinline__ float block_reduce_sum(float v, float* red) {
    __syncthreads();
    #pragma unroll
    for (int o = 16; o > 0; o >>= 1) v += __shfl_xor_sync(0xffffffffu, v, o);
    int t = threadIdx.x;
    if ((t & 31) == 0) red[t >> 5] = v;
    __syncthreads();
    if (t < 32) {
        int nw = blockDim.x >> 5;
        float r = (t < nw) ? red[t] : 0.f;
        #pragma unroll
        for (int o = 16; o > 0; o >>= 1) r += __shfl_xor_sync(0xffffffffu, r, o);
        if (t == 0) red[0] = r;
    }
    __syncthreads();
    return red[0];
}

__device__ __forceinline__ void cp16(uint32_t s, const void* g) {
    asm volatile("cp.async.cg.shared.global [%0], [%1], 16;" :: "r"(s), "l"(g));
}
__device__ __forceinline__ uint32_t smem_u32(const void* p) {
    uint32_t a;
    asm("{ .reg .u64 t; cvta.to.shared.u64 t, %1; cvt.u32.u64 %0, t; }" : "=r"(a) : "l"(p));
    return a;
}

__device__ __forceinline__ void mma_fp16(float* c, const uint32_t* a, const uint32_t* b) {
    asm volatile("mma.sync.aligned.m16n8k16.row.col.f32.f16.f16.f32 "
        "{%0,%1,%2,%3}, {%4,%5,%6,%7}, {%8,%9}, {%0,%1,%2,%3};"
        : "+f"(c[0]), "+f"(c[1]), "+f"(c[2]), "+f"(c[3])
        : "r"(a[0]), "r"(a[1]), "r"(a[2]), "r"(a[3]), "r"(b[0]), "r"(b[1]));
}

// ---------------- K0: weight row-norm scales ----------------
__global__ void scales_kernel(const float* __restrict__ wc, const float* __restrict__ wq,
                              const float* __restrict__ wo, const float* __restrict__ w1,
                              const float* __restrict__ w2) {
    int row = blockIdx.x;
    const float* w; int len; float inv_in; float* dst; int r;
    if (row < 1024)      { w = wc; len = 2048; inv_in = 1024.f; dst = g_s_cond; r = row; }
    else if (row < 2048) { w = wq; len = 3072; inv_in = 1024.f; dst = g_s_qkv;  r = row - 1024; }
    else if (row < 3072) { w = wo; len = 1024; inv_in = 1024.f; dst = g_s_out;  r = row - 2048; }
    else if (row < 4096) { w = w1; len = 4096; inv_in = 1024.f; dst = g_s_mlp1; r = row - 3072; }
    else                 { w = w2; len = 1024; inv_in = 4096.f; dst = g_s_mlp2; r = row - 4096; }
    const float* wr = w + (size_t)r * len;
    float ss = 0.f;
    for (int j = threadIdx.x; j < len; j += blockDim.x) { float v = wr[j]; ss += v * v; }
    __shared__ float red[32];
    ss = block_reduce_sum(ss, red);
    if (threadIdx.x == 0) {
        float norm = sqrtf(ss);
        dst[r] = 1.f / ((norm * sqrtf((float)len) + 1e-4f) * sqrtf(inv_in));
    }
}

// ---------------- transpose + scale-fold (x4096) -> fp16 ----------------
__global__ __launch_bounds__(256) void transpose_scale_kernel(const float* __restrict__ W,
                                                              const float* __restrict__ s,
                                                              __half* __restrict__ Wt,
                                                              int K, int N) {
    __shared__ float t[32][33];
    int k0 = blockIdx.y * 32, n0 = blockIdx.x * 32;
    int tx = threadIdx.x & 31, ty = threadIdx.x >> 5;
    #pragma unroll
    for (int i = 0; i < 32; i += 8) {
        int k = k0 + ty + i;
        t[ty + i][tx] = W[(size_t)k * N + n0 + tx] * (s[k] * WSCALE);
    }
    __syncthreads();
    #pragma unroll
    for (int i = 0; i < 32; i += 8)
        Wt[(size_t)(n0 + ty + i) * K + k0 + tx] = __float2half_rn(t[tx][ty + i]);
}

// ---------------- fp16 mma.sync GEMM: 128x256x64, 3-stage, warp tile 64x64 ----------------
// smem rows: 64 halves = 32 words + 4 pad = 36 words (144 B, 16B aligned)
#define SROW        36
#define SA_WORDS    (128 * SROW)
#define SB_WORDS    (256 * SROW)
#define STG_WORDS   (SA_WORDS + SB_WORDS)
#define GEMM_SMEM_BYTES (3 * STG_WORDS * 4)
__global__ __launch_bounds__(256, 1)
void gemm_mma_kernel(const __half* __restrict__ A, const __half* __restrict__ Bt,
                     float* __restrict__ C, int M, int N, int K) {
    extern __shared__ uint32_t smw[];
    int tid = threadIdx.x;
    int wid = tid >> 5, lane = tid & 31;
    int g = lane >> 2, j = lane & 3;
    int wm = wid >> 2, wn = wid & 3;      // 2 x 4 warps, warp tile 64x64
    int bm = blockIdx.y * 128;
    int bn = blockIdx.x * 256;
    uint32_t sb = smem_u32(smw);

    float acc[4][8][4];
    #pragma unroll
    for (int mt = 0; mt < 4; mt++)
        #pragma unroll
        for (int nt = 0; nt < 8; nt++)
            #pragma unroll
            for (int q = 0; q < 4; q++) acc[mt][nt][q] = 0.f;

    const int NC = K >> 6;  // chunks of 64 halves

    auto load_chunk = [&](int c, int stg) {
        uint32_t sA = sb + stg * (STG_WORDS * 4);
        uint32_t sB = sA + SA_WORDS * 4;
        int kc = c << 6;
        #pragma unroll
        for (int i = 0; i < 4; i++) {               // A: 1024 cp16 (128 rows x 8)
            int seg = tid + 256 * i;
            int row = seg >> 3, k8 = seg & 7;
            cp16(sA + row * (SROW * 4) + k8 * 16, A + (size_t)(bm + row) * K + kc + k8 * 8);
        }
        #pragma unroll
        for (int i = 0; i < 8; i++) {               // B: 2048 cp16 (256 rows x 8)
            int seg = tid + 256 * i;
            int row = seg >> 3, k8 = seg & 7;
            cp16(sB + row * (SROW * 4) + k8 * 16, Bt + (size_t)(bn + row) * K + kc + k8 * 8);
        }
    };

    load_chunk(0, 0);
    asm volatile("cp.async.commit_group;" ::: "memory");
    load_chunk(1, 1);
    asm volatile("cp.async.commit_group;" ::: "memory");

    for (int c = 0; c < NC; c++) {
        if (c < NC - 1) asm volatile("cp.async.wait_group 1;" ::: "memory");
        else            asm volatile("cp.async.wait_group 0;" ::: "memory");
        __syncthreads();

        int stg = c % 3;
        const uint32_t* uA = smw + stg * STG_WORDS;
        const uint32_t* uB = smw + stg * STG_WORDS + SA_WORDS;
        #pragma unroll
        for (int ks = 0; ks < 4; ks++) {            // k16 steps
            int k = ks * 8;
            uint32_t af[4][4];
            #pragma unroll
            for (int mt = 0; mt < 4; mt++) {
                int row = wm * 64 + mt * 16 + g;
                af[mt][0] = uA[row * SROW + k + j];
                af[mt][1] = uA[(row + 8) * SROW + k + j];
                af[mt][2] = uA[row * SROW + k + j + 4];
                af[mt][3] = uA[(row + 8) * SROW + k + j + 4];
            }
            #pragma unroll
            for (int nt = 0; nt < 8; nt++) {
                int n = wn * 64 + nt * 8 + g;
                uint32_t bfr[2];
                bfr[0] = uB[n * SROW + k + j];
                bfr[1] = uB[n * SROW + k + j + 4];
                #pragma unroll
                for (int mt = 0; mt < 4; mt++)
                    mma_fp16(acc[mt][nt], af[mt], bfr);
            }
        }

        if (c + 2 < NC) {
            load_chunk(c + 2, (c + 2) % 3);
            asm volatile("cp.async.commit_group;" ::: "memory");
        }
    }

    #pragma unroll
    for (int mt = 0; mt < 4; mt++) {
        int row = bm + wm * 64 + mt * 16 + g;
        #pragma unroll
        for (int nt = 0; nt < 8; nt++) {
            int col = bn + wn * 64 + nt * 8 + 2 * j;
            float2 o0 = {acc[mt][nt][0], acc[mt][nt][1]};
            float2 o1 = {acc[mt][nt][2], acc[mt][nt][3]};
            *(float2*)(C + (size_t)row * N + col) = o0;
            *(float2*)(C + (size_t)(row + 8) * N + col) = o1;
        }
    }
}

// ---------------- K1: conditioning GEMM, split-K + reduce ----------------
__global__ __launch_bounds__(256) void cond_part_kernel(const float* __restrict__ c,
                                                        const float* __restrict__ w_cond) {
    __shared__ float ccs[4][64];
    int tid = threadIdx.x;
    int i0 = blockIdx.y * 64;
    {
        int bb = tid >> 6, ii = tid & 63;
        float v = c[bb * 1024 + i0 + ii];
        float sil = v / (1.f + expf(-v)) * INV_0596;
        ccs[bb][ii] = sil * g_s_cond[i0 + ii];
    }
    __syncthreads();
    int j = blockIdx.x * 256 + tid;
    float a0 = 0.f, a1 = 0.f, a2 = 0.f, a3 = 0.f;
    #pragma unroll 4
    for (int i = 0; i < 64; i++) {
        float w = w_cond[(size_t)(i0 + i) * 2048 + j];
        a0 += ccs[0][i] * w; a1 += ccs[1][i] * w;
        a2 += ccs[2][i] * w; a3 += ccs[3][i] * w;
    }
    g_cpart[blockIdx.y][0][j] = a0;
    g_cpart[blockIdx.y][1][j] = a1;
    g_cpart[blockIdx.y][2][j] = a2;
    g_cpart[blockIdx.y][3][j] = a3;
}

__global__ __launch_bounds__(256) void cond_reduce_kernel() {
    int idx = blockIdx.x * 256 + threadIdx.x;
    int bb = idx >> 11, j = idx & 2047;
    float a = 0.f;
    #pragma unroll
    for (int s = 0; s < 16; s++) a += g_cpart[s][bb][j];
    if (j < 1024) g_gain[bb * 1024 + j] = a;
    else          g_shift[bb * 1024 + (j - 1024)] = a;
}

// ---------------- K2: x_cond -> fp16 ----------------
__global__ __launch_bounds__(256) void xcond_kernel(const float* __restrict__ x) {
    int r = blockIdx.x; int b = r >> 10;
    const float* xr = x + (size_t)r * HIDD;
    int e = threadIdx.x * 4;
    float4 v = *(const float4*)(xr + e);
    float ss = v.x * v.x + v.y * v.y + v.z * v.z + v.w * v.w;
    __shared__ float red[32];
    ss = block_reduce_sum(ss, red);
    float rs = rsqrtf(ss * (1.f / 1024.f) + 1e-4f);
    const float* gn = g_gain + b * 1024; const float* sh = g_shift + b * 1024;
    float o0 = v.x * rs * (1.f + gn[e + 0]) + sh[e + 0];
    float o1 = v.y * rs * (1.f + gn[e + 1]) + sh[e + 1];
    float o2 = v.z * rs * (1.f + gn[e + 2]) + sh[e + 2];
    float o3 = v.w * rs * (1.f + gn[e + 3]) + sh[e + 3];
    __half2* dst = (__half2*)(g_xcondh + (size_t)r * HIDD + e);
    dst[0] = __floats2half2_rn(o0, o1);
    dst[1] = __floats2half2_rn(o2, o3);
}

// ---------------- K3: q/k normalization -> fp16, + v scale ----------------
__global__ __launch_bounds__(256) void qkvnorm_kernel() {
    int r = blockIdx.x; int b = r >> 10, n = r & 1023;
    const float* row = g_qkv + (size_t)r * 3072;
    int t = threadIdx.x, e = t * 4, head = t >> 4;
    float4 q = *(const float4*)(row + e);
    float4 k = *(const float4*)(row + 1024 + e);
    float4 v = *(const float4*)(row + 2048 + e);
    q.x *= INV_WS; q.y *= INV_WS; q.z *= INV_WS; q.w *= INV_WS;
    k.x *= INV_WS; k.y *= INV_WS; k.z *= INV_WS; k.w *= INV_WS;
    v.x *= INV_WS; v.y *= INV_WS; v.z *= INV_WS; v.w *= INV_WS;
    __shared__ float hq[16], hk[16], hv[16];
    if (t < 16) { hq[t] = 0.f; hk[t] = 0.f; hv[t] = 0.f; }
    __syncthreads();
    float sq = q.x * q.x + q.y * q.y + q.z * q.z + q.w * q.w;
    float sk = k.x * k.x + k.y * k.y + k.z * k.z + k.w * k.w;
    float sv = v.x * v.x + v.y * v.y + v.z * v.z + v.w * v.w;
    atomicAdd(&hq[head], sq); atomicAdd(&hk[head], sk); atomicAdd(&hv[head], sv);
    __syncthreads();
    float tq = 0.f, tk = 0.f, tv = 0.f;
    #pragma unroll
    for (int h = 0; h < 16; h++) { tq += hq[h]; tk += hk[h]; tv += hv[h]; }
    float pq = rsqrtf(tq * (1.f / 1024.f) + 1e-4f);
    float pk = rsqrtf(tk * (1.f / 1024.f) + 1e-4f);
    float pv = rsqrtf(tv * (1.f / 1024.f) + 1e-4f);
    float qs = pq * rsqrtf(pq * pq * hq[head] + 1e-6f) * 0.125f;
    float ks = pk * rsqrtf(pk * pk * hk[head] + 1e-6f);
    if (t == 0) g_pv[r] = pv * INV_WS;   // folded unscale for vtrans
    size_t base = ((size_t)(b * 16 + head) * 1024 + n) * 64 + (e & 63);
    __half2* qd = (__half2*)(g_qh + base);
    __half2* kd = (__half2*)(g_kh + base);
    qd[0] = __floats2half2_rn(q.x * qs, q.y * qs);
    qd[1] = __floats2half2_rn(q.z * qs, q.w * qs);
    kd[0] = __floats2half2_rn(k.x * ks, k.y * ks);
    kd[1] = __floats2half2_rn(k.z * ks, k.w * ks);
}

// ---------------- V transpose -> fp16 [bh][d][n] ----------------
__global__ __launch_bounds__(256) void vtrans_kernel() {
    __shared__ float t[32][33];
    int bh = blockIdx.z; int b = bh >> 4, h = bh & 15;
    int n0 = blockIdx.x * 32, d0 = blockIdx.y * 32;
    int tx = threadIdx.x & 31, ty = threadIdx.x >> 5;
    #pragma unroll
    for (int i = 0; i < 32; i += 8) {
        int n = n0 + ty + i;
        int rowg = b * 1024 + n;
        t[ty + i][tx] = g_qkv[(size_t)rowg * 3072 + 2048 + h * 64 + d0 + tx] * g_pv[rowg];
    }
    __syncthreads();
    #pragma unroll
    for (int i = 0; i < 32; i += 8) {
        int d = d0 + ty + i;
        g_vth[((size_t)bh * 64 + d) * 1024 + n0 + tx] = __float2half_rn(t[tx][ty + i]);
    }
}

// ---------------- K4: flash attention via fp16 mma.sync ----------------
// smem rows: 64 halves = 32 words + 4 pad = 36 words per row
#define AT_SROW 36
#define AT_BUF  (64 * AT_SROW)                 // words per buffer
#define ATT_SMEM_BYTES (4 * AT_BUF * 4)        // 36,864 B
__global__ __launch_bounds__(128, 4) void attn_mma_kernel() {
    extern __shared__ uint32_t smw[];
    uint32_t* uQ  = smw;
    uint32_t* uK  = smw + AT_BUF;
    uint32_t* uVt = smw + 2 * AT_BUF;
    uint32_t* uP  = smw + 3 * AT_BUF;

    int tid = threadIdx.x;
    int w = tid >> 5, lane = tid & 31;
    int g = lane >> 2, j = lane & 3;
    int bh = blockIdx.y;
    int n0 = blockIdx.x * 64;
    const __half* qb  = g_qh + ((size_t)bh * 1024 + n0) * 64;
    const __half* kb  = g_kh + (size_t)bh * 1024 * 64;
    const __half* vtb = g_vth + (size_t)bh * 64 * 1024;

    #pragma unroll
    for (int i = 0; i < 4; i++) {               // Q: 512 x 16B
        int seg = tid + 128 * i;
        int row = seg >> 3, k8 = seg & 7;
        *(uint4*)(uQ + row * AT_SROW + k8 * 4) = *(const uint4*)(qb + row * 64 + k8 * 8);
    }

    float accO[8][4];
    #pragma unroll
    for (int nt = 0; nt < 8; nt++)
        #pragma unroll
        for (int q = 0; q < 4; q++) accO[nt][q] = 0.f;
    float mi0 = -INFINITY, mi1 = -INFINITY, li0 = 0.f, li1 = 0.f;

    for (int kt = 0; kt < 16; kt++) {
        __syncthreads();
        const __half* kb0 = kb + (size_t)kt * 64 * 64;
        #pragma unroll
        for (int i = 0; i < 4; i++) {
            int seg = tid + 128 * i;
            int row = seg >> 3, k8 = seg & 7;
            *(uint4*)(uK + row * AT_SROW + k8 * 4) = *(const uint4*)(kb0 + row * 64 + k8 * 8);
            *(uint4*)(uVt + row * AT_SROW + k8 * 4) =
                *(const uint4*)(vtb + row * 1024 + kt * 64 + k8 * 8);
        }
        __syncthreads();

        // S = Q @ K^T  (warp rows w*16..+15, 64 keys), k16 x 4
        float accS[8][4];
        #pragma unroll
        for (int nt = 0; nt < 8; nt++)
            #pragma unroll
            for (int q = 0; q < 4; q++) accS[nt][q] = 0.f;
        #pragma unroll
        for (int ks = 0; ks < 4; ks++) {
            int k = ks * 8;
            uint32_t a[4];
            int r0 = (w * 16 + g) * AT_SROW, r1 = (w * 16 + g + 8) * AT_SROW;
            a[0] = uQ[r0 + k + j];
            a[1] = uQ[r1 + k + j];
            a[2] = uQ[r0 + k + j + 4];
            a[3] = uQ[r1 + k + j + 4];
            #pragma unroll
            for (int nt = 0; nt < 8; nt++) {
                uint32_t bfr[2];
                bfr[0] = uK[(nt * 8 + g) * AT_SROW + k + j];
                bfr[1] = uK[(nt * 8 + g) * AT_SROW + k + j + 4];
                mma_fp16(accS[nt], a, bfr);
            }
        }

        // online softmax (rows g / g+8)
        float mx0 = -INFINITY, mx1 = -INFINITY;
        #pragma unroll
        for (int nt = 0; nt < 8; nt++) {
            mx0 = fmaxf(mx0, fmaxf(accS[nt][0], accS[nt][1]));
            mx1 = fmaxf(mx1, fmaxf(accS[nt][2], accS[nt][3]));
        }
        mx0 = fmaxf(mx0, __shfl_xor_sync(0xffffffffu, mx0, 1));
        mx0 = fmaxf(mx0, __shfl_xor_sync(0xffffffffu, mx0, 2));
        mx1 = fmaxf(mx1, __shfl_xor_sync(0xffffffffu, mx1, 1));
        mx1 = fmaxf(mx1, __shfl_xor_sync(0xffffffffu, mx1, 2));
        float nm0 = fmaxf(mi0, mx0), nm1 = fmaxf(mi1, mx1);
        float corr0 = __expf(mi0 - nm0), corr1 = __expf(mi1 - nm1);
        float ps0 = 0.f, ps1 = 0.f;
        #pragma unroll
        for (int nt = 0; nt < 8; nt++) {
            float p0 = __expf(accS[nt][0] - nm0);
            float p1 = __expf(accS[nt][1] - nm0);
            float p2 = __expf(accS[nt][2] - nm1);
            float p3 = __expf(accS[nt][3] - nm1);
            accS[nt][0] = p0; accS[nt][1] = p1; accS[nt][2] = p2; accS[nt][3] = p3;
            ps0 += p0 + p1; ps1 += p2 + p3;
        }
        ps0 += __shfl_xor_sync(0xffffffffu, ps0, 1);
        ps0 += __shfl_xor_sync(0xffffffffu, ps0, 2);
        ps1 += __shfl_xor_sync(0xffffffffu, ps1, 1);
        ps1 += __shfl_xor_sync(0xffffffffu, ps1, 2);
        li0 = li0 * corr0 + ps0; mi0 = nm0;
        li1 = li1 * corr1 + ps1; mi1 = nm1;
        #pragma unroll
        for (int nt = 0; nt < 8; nt++) {
            accO[nt][0] *= corr0; accO[nt][1] *= corr0;
            accO[nt][2] *= corr1; accO[nt][3] *= corr1;
        }

        // P -> smem as fp16 (per-warp private rows)
        #pragma unroll
        for (int nt = 0; nt < 8; nt++) {
            ((__half2*)uP)[(w * 16 + g) * AT_SROW + nt * 4 + j] =
                __floats2half2_rn(accS[nt][0], accS[nt][1]);
            ((__half2*)uP)[(w * 16 + g + 8) * AT_SROW + nt * 4 + j] =
                __floats2half2_rn(accS[nt][2], accS[nt][3]);
        }
        __syncwarp();

        // O += P @ V  (Vt[d][keys]), k16 x 4
        #pragma unroll
        for (int ks = 0; ks < 4; ks++) {
            int k = ks * 8;
            uint32_t a[4];
            int r0 = (w * 16 + g) * AT_SROW, r1 = (w * 16 + g + 8) * AT_SROW;
            a[0] = uP[r0 + k + j];
            a[1] = uP[r1 + k + j];
            a[2] = uP[r0 + k + j + 4];
            a[3] = uP[r1 + k + j + 4];
            #pragma unroll
            for (int nt = 0; nt < 8; nt++) {
                uint32_t bfr[2];
                bfr[0] = uVt[(nt * 8 + g) * AT_SROW + k + j];
                bfr[1] = uVt[(nt * 8 + g) * AT_SROW + k + j + 4];
                mma_fp16(accO[nt], a, bfr);
            }
        }
    }

    float inv0 = 1.f / li0, inv1 = 1.f / li1;
    int b = bh >> 4, h = bh & 15;
    int row0 = b * 1024 + n0 + w * 16 + g;
    #pragma unroll
    for (int nt = 0; nt < 8; nt++) {
        int col = h * 64 + nt * 8 + 2 * j;
        *(__half2*)(g_attnh + (size_t)row0 * HIDD + col) =
            __floats2half2_rn(accO[nt][0] * inv0, accO[nt][1] * inv0);
        *(__half2*)(g_attnh + (size_t)(row0 + 8) * HIDD + col) =
            __floats2half2_rn(accO[nt][2] * inv1, accO[nt][3] * inv1);
    }
}

// ---------------- K5: attn epilogue + residual + second x_cond ----------------
__global__ __launch_bounds__(256) void post_attn_kernel(const float* __restrict__ x,
                                                        const float* __restrict__ attn_gain) {
    int r = blockIdx.x, b = r >> 10;
    int e = threadIdx.x * 4;
    float4 y = *(const float4*)(g_tmp + (size_t)r * HIDD + e);
    y.x *= INV_WS; y.y *= INV_WS; y.z *= INV_WS; y.w *= INV_WS;
    __shared__ float red[32];
    float ss = y.x * y.x + y.y * y.y + y.z * y.z + y.w * y.w;
    ss = block_reduce_sum(ss, red);
    float py = rsqrtf(ss * (1.f / 1024.f) + 1e-4f) * expf(attn_gain[0]);
    float4 xv = *(const float4*)(x + (size_t)r * HIDD + e);
    float4 x1;
    x1.x = (0.7f * xv.x + 0.3f * (y.x * py)) * RSQRT058;
    x1.y = (0.7f * xv.y + 0.3f * (y.y * py)) * RSQRT058;
    x1.z = (0.7f * xv.z + 0.3f * (y.z * py)) * RSQRT058;
    x1.w = (0.7f * xv.w + 0.3f * (y.w * py)) * RSQRT058;
    *(float4*)(g_x1 + (size_t)r * HIDD + e) = x1;
    float ss1 = x1.x * x1.x + x1.y * x1.y + x1.z * x1.z + x1.w * x1.w;
    ss1 = block_reduce_sum(ss1, red);
    float p1 = rsqrtf(ss1 * (1.f / 1024.f) + 1e-4f);
    const float* gn = g_gain + b * 1024; const float* sh = g_shift + b * 1024;
    float o0 = x1.x * p1 * (1.f + gn[e + 0]) + sh[e + 0];
    float o1 = x1.y * p1 * (1.f + gn[e + 1]) + sh[e + 1];
    float o2 = x1.z * p1 * (1.f + gn[e + 2]) + sh[e + 2];
    float o3 = x1.w * p1 * (1.f + gn[e + 3]) + sh[e + 3];
    __half2* dst = (__half2*)(g_xcondh + (size_t)r * HIDD + e);
    dst[0] = __floats2half2_rn(o0, o1);
    dst[1] = __floats2half2_rn(o2, o3);
}

// ---------------- K6: MLP hidden activation -> fp16 ----------------
__global__ __launch_bounds__(256) void mlp_act_kernel() {
    int r = blockIdx.x;
    const float* row = g_h + (size_t)r * MLPD;
    __half* rowh = g_hh + (size_t)r * MLPD;
    float4 v[4];
    float ss = 0.f;
    #pragma unroll
    for (int i = 0; i < 4; i++) {
        v[i] = *(const float4*)(row + (threadIdx.x + 256 * i) * 4);
        v[i].x *= INV_WS; v[i].y *= INV_WS; v[i].z *= INV_WS; v[i].w *= INV_WS;
        ss += v[i].x * v[i].x + v[i].y * v[i].y + v[i].z * v[i].z + v[i].w * v[i].w;
    }
    __shared__ float red[32];
    ss = block_reduce_sum(ss, red);
    float ps = rsqrtf(ss * (1.f / 4096.f) + 1e-4f);
    #pragma unroll
    for (int i = 0; i < 4; i++) {
        float u0 = v[i].x * ps, u1 = v[i].y * ps, u2 = v[i].z * ps, u3 = v[i].w * ps;
        float o0 = u0 / (1.f + expf(-u0)) * INV_0596;
        float o1 = u1 / (1.f + expf(-u1)) * INV_0596;
        float o2 = u2 / (1.f + expf(-u2)) * INV_0596;
        float o3 = u3 / (1.f + expf(-u3)) * INV_0596;
        __half2* dst = (__half2*)(rowh + (threadIdx.x + 256 * i) * 4);
        dst[0] = __floats2half2_rn(o0, o1);
        dst[1] = __floats2half2_rn(o2, o3);
    }
}

// ---------------- K7: final epilogue ----------------
__global__ __launch_bounds__(256) void final_kernel(const float* __restrict__ mlp_gain,
                                                    float* __restrict__ out) {
    int r = blockIdx.x;
    int e = threadIdx.x * 4;
    float4 y = *(const float4*)(g_tmp + (size_t)r * HIDD + e);
    y.x *= INV_WS; y.y *= INV_WS; y.z *= INV_WS; y.w *= INV_WS;
    __shared__ float red[32];
    float ss = y.x * y.x + y.y * y.y + y.z * y.z + y.w * y.w;
    ss = block_reduce_sum(ss, red);
    float pm = rsqrtf(ss * (1.f / 1024.f) + 1e-4f) * expf(mlp_gain[0]);
    float4 x1 = *(const float4*)(g_x1 + (size_t)r * HIDD + e);
    float4 o;
    o.x = (0.7f * x1.x + 0.3f * (y.x * pm)) * RSQRT058;
    o.y = (0.7f * x1.y + 0.3f * (y.y * pm)) * RSQRT058;
    o.z = (0.7f * x1.z + 0.3f * (y.z * pm)) * RSQRT058;
    o.w = (0.7f * x1.w + 0.3f * (y.w * pm)) * RSQRT058;
    *(float4*)(out + (size_t)r * HIDD + e) = o;
}

// ---------------- launch ----------------
extern "C" void kernel_launch(void* const* d_in, const int* in_sizes, int n_in,
                              void* d_out, int out_size) {
    const float* x        = (const float*)d_in[0];
    const float* c        = (const float*)d_in[1];
    const float* w_cond   = (const float*)d_in[2];
    const float* w_qkv    = (const float*)d_in[3];
    const float* w_out    = (const float*)d_in[4];
    const float* w_mlp1   = (const float*)d_in[5];
    const float* w_mlp2   = (const float*)d_in[6];
    const float* attn_gain = (const float*)d_in[7];
    const float* mlp_gain  = (const float*)d_in[8];
    float* out = (float*)d_out;

    void* p;
    cudaGetSymbolAddress(&p, g_xcondh); __half* xcondh = (__half*)p;
    cudaGetSymbolAddress(&p, g_qkv);    float* qkv   = (float*)p;
    cudaGetSymbolAddress(&p, g_attnh);  __half* attnh = (__half*)p;
    cudaGetSymbolAddress(&p, g_h);      float* hbuf  = (float*)p;
    cudaGetSymbolAddress(&p, g_hh);     __half* hh   = (__half*)p;
    cudaGetSymbolAddress(&p, g_tmp);    float* tmp   = (float*)p;
    cudaGetSymbolAddress(&p, g_s_qkv);  float* sqkv  = (float*)p;
    cudaGetSymbolAddress(&p, g_s_out);  float* sout  = (float*)p;
    cudaGetSymbolAddress(&p, g_s_mlp1); float* smlp1 = (float*)p;
    cudaGetSymbolAddress(&p, g_s_mlp2); float* smlp2 = (float*)p;
    cudaGetSymbolAddress(&p, g_wtq);    __half* wtq  = (__half*)p;
    cudaGetSymbolAddress(&p, g_wto);    __half* wto  = (__half*)p;
    cudaGetSymbolAddress(&p, g_wt1);    __half* wt1  = (__half*)p;
    cudaGetSymbolAddress(&p, g_wt2);    __half* wt2  = (__half*)p;

    cudaFuncSetAttribute(attn_mma_kernel, cudaFuncAttributeMaxDynamicSharedMemorySize,
                         ATT_SMEM_BYTES);
    cudaFuncSetAttribute(gemm_mma_kernel, cudaFuncAttributeMaxDynamicSharedMemorySize,
                         GEMM_SMEM_BYTES);

    scales_kernel<<<8192, 128>>>(w_cond, w_qkv, w_out, w_mlp1, w_mlp2);
    cond_part_kernel<<<dim3(8, 16), 256>>>(c, w_cond);
    cond_reduce_kernel<<<32, 256>>>();
    transpose_scale_kernel<<<dim3(3072 / 32, 1024 / 32), 256>>>(w_qkv, sqkv, wtq, 1024, 3072);
    transpose_scale_kernel<<<dim3(1024 / 32, 1024 / 32), 256>>>(w_out, sout, wto, 1024, 1024);
    transpose_scale_kernel<<<dim3(4096 / 32, 1024 / 32), 256>>>(w_mlp1, smlp1, wt1, 1024, 4096);
    transpose_scale_kernel<<<dim3(1024 / 32, 4096 / 32), 256>>>(w_mlp2, smlp2, wt2, 4096, 1024);

    xcond_kernel<<<4096, 256>>>(x);
    gemm_mma_kernel<<<dim3(12, 32), 256, GEMM_SMEM_BYTES>>>(xcondh, wtq, qkv, 4096, 3072, 1024);
    qkvnorm_kernel<<<4096, 256>>>();
    vtrans_kernel<<<dim3(32, 2, 64), 256>>>();
    attn_mma_kernel<<<dim3(16, 64), 128, ATT_SMEM_BYTES>>>();
    gemm_mma_kernel<<<dim3(4, 32), 256, GEMM_SMEM_BYTES>>>(attnh, wto, tmp, 4096, 1024, 1024);
    post_attn_kernel<<<4096, 256>>>(x, attn_gain);
    gemm_mma_kernel<<<dim3(16, 32), 256, GEMM_SMEM_BYTES>>>(xcondh, wt1, hbuf, 4096, 4096, 1024);
    mlp_act_kernel<<<4096, 256>>>();
    gemm_mma_kernel<<<dim3(4, 32), 256, GEMM_SMEM_BYTES>>>(hh, wt2, tmp, 4096, 1024, 4096);
    final_kernel<<<4096, 256>>>(mlp_gain, out);
}

// round 9
// speedup vs baseline: 6.2053x; 1.0455x over previous
#include <cuda_runtime.h>
#include <cuda_fp16.h>
#include <math.h>
#include <stdint.h>

// ---------------- problem constants ----------------
#define BNROWS 4096
#define HIDD   1024
#define MLPD   4096

#define INV_0596 1.6778523489932886f
#define RSQRT058 1.3130643285972254f
#define WSCALE   4096.0f
#define INV_WS   (1.0f / 4096.0f)

// ---------------- scratch ----------------
__device__ float g_s_cond[1024];
__device__ float g_s_qkv[1024];
__device__ float g_s_out[1024];
__device__ float g_s_mlp1[1024];
__device__ float g_s_mlp2[4096];
__device__ float g_gain[4 * 1024];
__device__ float g_shift[4 * 1024];
__device__ float g_cpart[16][4][2048];
__device__ float g_pv[BNROWS];
__device__ float g_x1[BNROWS * HIDD];
__device__ float g_ssp[(size_t)BNROWS * 64];      // per-row partial sum-of-squares
// fp16 buffers
__device__ __half g_xcondh[BNROWS * HIDD];
__device__ __half g_qkvh[BNROWS * 3072];
__device__ __half g_attnh[BNROWS * HIDD];
__device__ __half g_tmph[BNROWS * HIDD];
__device__ __half g_hh[(size_t)BNROWS * MLPD];
__device__ __half g_qh[64 * 1024 * 64];
__device__ __half g_kh[64 * 1024 * 64];
__device__ __half g_vth[64 * 64 * 1024];          // [bh][d][n]
// transposed + scaled (x4096) fp16 weights [N][K]
__device__ __half g_wtq[3072 * 1024];
__device__ __half g_wto[1024 * 1024];
__device__ __half g_wt1[4096 * 1024];
__device__ __half g_wt2[1024 * 4096];

// ---------------- helpers ----------------
__device__ __forceinline__ float block_reduce_sum(float v, float* red) {
    __syncthreads();
    #pragma unroll
    for (int o = 16; o > 0; o >>= 1) v += __shfl_xor_sync(0xffffffffu, v, o);
    int t = threadIdx.x;
    if ((t & 31) == 0) red[t >> 5] = v;
    __syncthreads();
    if (t < 32) {
        int nw = blockDim.x >> 5;
        float r = (t < nw) ? red[t] : 0.f;
        #pragma unroll
        for (int o = 16; o > 0; o >>= 1) r += __shfl_xor_sync(0xffffffffu, r, o);
        if (t == 0) red[0] = r;
    }
    __syncthreads();
    return red[0];
}

__device__ __forceinline__ void cp16(uint32_t s, const void* g) {
    asm volatile("cp.async.cg.shared.global [%0], [%1], 16;" :: "r"(s), "l"(g));
}
__device__ __forceinline__ uint32_t smem_u32(const void* p) {
    uint32_t a;
    asm("{ .reg .u64 t; cvta.to.shared.u64 t, %1; cvt.u32.u64 %0, t; }" : "=r"(a) : "l"(p));
    return a;
}

__device__ __forceinline__ void mma_fp16(float* c, const uint32_t* a, const uint32_t* b) {
    asm volatile("mma.sync.aligned.m16n8k16.row.col.f32.f16.f16.f32 "
        "{%0,%1,%2,%3}, {%4,%5,%6,%7}, {%8,%9}, {%0,%1,%2,%3};"
        : "+f"(c[0]), "+f"(c[1]), "+f"(c[2]), "+f"(c[3])
        : "r"(a[0]), "r"(a[1]), "r"(a[2]), "r"(a[3]), "r"(b[0]), "r"(b[1]));
}

// ---------------- K0: weight row-norm scales ----------------
__global__ void scales_kernel(const float* __restrict__ wc, const float* __restrict__ wq,
                              const float* __restrict__ wo, const float* __restrict__ w1,
                              const float* __restrict__ w2) {
    int row = blockIdx.x;
    const float* w; int len; float inv_in; float* dst; int r;
    if (row < 1024)      { w = wc; len = 2048; inv_in = 1024.f; dst = g_s_cond; r = row; }
    else if (row < 2048) { w = wq; len = 3072; inv_in = 1024.f; dst = g_s_qkv;  r = row - 1024; }
    else if (row < 3072) { w = wo; len = 1024; inv_in = 1024.f; dst = g_s_out;  r = row - 2048; }
    else if (row < 4096) { w = w1; len = 4096; inv_in = 1024.f; dst = g_s_mlp1; r = row - 3072; }
    else                 { w = w2; len = 1024; inv_in = 4096.f; dst = g_s_mlp2; r = row - 4096; }
    const float* wr = w + (size_t)r * len;
    float ss = 0.f;
    for (int j = threadIdx.x; j < len; j += blockDim.x) { float v = wr[j]; ss += v * v; }
    __shared__ float red[32];
    ss = block_reduce_sum(ss, red);
    if (threadIdx.x == 0) {
        float norm = sqrtf(ss);
        dst[r] = 1.f / ((norm * sqrtf((float)len) + 1e-4f) * sqrtf(inv_in));
    }
}

// ---------------- transpose + scale-fold (x4096) -> fp16 ----------------
__global__ __launch_bounds__(256) void transpose_scale_kernel(const float* __restrict__ W,
                                                              const float* __restrict__ s,
                                                              __half* __restrict__ Wt,
                                                              int K, int N) {
    __shared__ float t[32][33];
    int k0 = blockIdx.y * 32, n0 = blockIdx.x * 32;
    int tx = threadIdx.x & 31, ty = threadIdx.x >> 5;
    #pragma unroll
    for (int i = 0; i < 32; i += 8) {
        int k = k0 + ty + i;
        t[ty + i][tx] = W[(size_t)k * N + n0 + tx] * (s[k] * WSCALE);
    }
    __syncthreads();
    #pragma unroll
    for (int i = 0; i < 32; i += 8)
        Wt[(size_t)(n0 + ty + i) * K + k0 + tx] = __float2half_rn(t[tx][ty + i]);
}

// ---------------- fp16 mma.sync GEMM: 128x256x64, 3-stage, warp tile 64x64 ----------------
// C written as fp16 (unscaled by INV_WS); optional per-row partial SS to ssp[row*64 + bx*4 + wn].
#define SROW        36
#define SA_WORDS    (128 * SROW)
#define SB_WORDS    (256 * SROW)
#define STG_WORDS   (SA_WORDS + SB_WORDS)
#define GEMM_SMEM_BYTES (3 * STG_WORDS * 4)
__global__ __launch_bounds__(256, 1)
void gemm_mma_kernel(const __half* __restrict__ A, const __half* __restrict__ Bt,
                     __half* __restrict__ C, float* __restrict__ ssp,
                     int M, int N, int K) {
    extern __shared__ uint32_t smw[];
    int tid = threadIdx.x;
    int wid = tid >> 5, lane = tid & 31;
    int g = lane >> 2, j = lane & 3;
    int wm = wid >> 2, wn = wid & 3;
    int bm = blockIdx.y * 128;
    int bn = blockIdx.x * 256;
    uint32_t sb = smem_u32(smw);

    float acc[4][8][4];
    #pragma unroll
    for (int mt = 0; mt < 4; mt++)
        #pragma unroll
        for (int nt = 0; nt < 8; nt++)
            #pragma unroll
            for (int q = 0; q < 4; q++) acc[mt][nt][q] = 0.f;

    const int NC = K >> 6;

    auto load_chunk = [&](int c, int stg) {
        uint32_t sA = sb + stg * (STG_WORDS * 4);
        uint32_t sB = sA + SA_WORDS * 4;
        int kc = c << 6;
        #pragma unroll
        for (int i = 0; i < 4; i++) {
            int seg = tid + 256 * i;
            int row = seg >> 3, k8 = seg & 7;
            cp16(sA + row * (SROW * 4) + k8 * 16, A + (size_t)(bm + row) * K + kc + k8 * 8);
        }
        #pragma unroll
        for (int i = 0; i < 8; i++) {
            int seg = tid + 256 * i;
            int row = seg >> 3, k8 = seg & 7;
            cp16(sB + row * (SROW * 4) + k8 * 16, Bt + (size_t)(bn + row) * K + kc + k8 * 8);
        }
    };

    load_chunk(0, 0);
    asm volatile("cp.async.commit_group;" ::: "memory");
    load_chunk(1, 1);
    asm volatile("cp.async.commit_group;" ::: "memory");

    for (int c = 0; c < NC; c++) {
        if (c < NC - 1) asm volatile("cp.async.wait_group 1;" ::: "memory");
        else            asm volatile("cp.async.wait_group 0;" ::: "memory");
        __syncthreads();

        int stg = c % 3;
        const uint32_t* uA = smw + stg * STG_WORDS;
        const uint32_t* uB = smw + stg * STG_WORDS + SA_WORDS;
        #pragma unroll
        for (int ks = 0; ks < 4; ks++) {
            int k = ks * 8;
            uint32_t af[4][4];
            #pragma unroll
            for (int mt = 0; mt < 4; mt++) {
                int row = wm * 64 + mt * 16 + g;
                af[mt][0] = uA[row * SROW + k + j];
                af[mt][1] = uA[(row + 8) * SROW + k + j];
                af[mt][2] = uA[row * SROW + k + j + 4];
                af[mt][3] = uA[(row + 8) * SROW + k + j + 4];
            }
            #pragma unroll
            for (int nt = 0; nt < 8; nt++) {
                int n = wn * 64 + nt * 8 + g;
                uint32_t bfr[2];
                bfr[0] = uB[n * SROW + k + j];
                bfr[1] = uB[n * SROW + k + j + 4];
                #pragma unroll
                for (int mt = 0; mt < 4; mt++)
                    mma_fp16(acc[mt][nt], af[mt], bfr);
            }
        }

        if (c + 2 < NC) {
            load_chunk(c + 2, (c + 2) % 3);
            asm volatile("cp.async.commit_group;" ::: "memory");
        }
    }

    #pragma unroll
    for (int mt = 0; mt < 4; mt++) {
        int row = bm + wm * 64 + mt * 16 + g;
        float s0 = 0.f, s1 = 0.f;
        #pragma unroll
        for (int nt = 0; nt < 8; nt++) {
            int col = bn + wn * 64 + nt * 8 + 2 * j;
            float c0 = acc[mt][nt][0] * INV_WS, c1 = acc[mt][nt][1] * INV_WS;
            float c2 = acc[mt][nt][2] * INV_WS, c3 = acc[mt][nt][3] * INV_WS;
            *(__half2*)(C + (size_t)row * N + col) = __floats2half2_rn(c0, c1);
            *(__half2*)(C + (size_t)(row + 8) * N + col) = __floats2half2_rn(c2, c3);
            s0 += c0 * c0 + c1 * c1;
            s1 += c2 * c2 + c3 * c3;
        }
        if (ssp) {
            s0 += __shfl_xor_sync(0xffffffffu, s0, 1);
            s0 += __shfl_xor_sync(0xffffffffu, s0, 2);
            s1 += __shfl_xor_sync(0xffffffffu, s1, 1);
            s1 += __shfl_xor_sync(0xffffffffu, s1, 2);
            if (j == 0) {
                ssp[(size_t)row * 64 + blockIdx.x * 4 + wn] = s0;
                ssp[(size_t)(row + 8) * 64 + blockIdx.x * 4 + wn] = s1;
            }
        }
    }
}

// ---------------- K1: conditioning GEMM, split-K + reduce ----------------
__global__ __launch_bounds__(256) void cond_part_kernel(const float* __restrict__ c,
                                                        const float* __restrict__ w_cond) {
    __shared__ float ccs[4][64];
    int tid = threadIdx.x;
    int i0 = blockIdx.y * 64;
    {
        int bb = tid >> 6, ii = tid & 63;
        float v = c[bb * 1024 + i0 + ii];
        float sil = v / (1.f + expf(-v)) * INV_0596;
        ccs[bb][ii] = sil * g_s_cond[i0 + ii];
    }
    __syncthreads();
    int j = blockIdx.x * 256 + tid;
    float a0 = 0.f, a1 = 0.f, a2 = 0.f, a3 = 0.f;
    #pragma unroll 4
    for (int i = 0; i < 64; i++) {
        float w = w_cond[(size_t)(i0 + i) * 2048 + j];
        a0 += ccs[0][i] * w; a1 += ccs[1][i] * w;
        a2 += ccs[2][i] * w; a3 += ccs[3][i] * w;
    }
    g_cpart[blockIdx.y][0][j] = a0;
    g_cpart[blockIdx.y][1][j] = a1;
    g_cpart[blockIdx.y][2][j] = a2;
    g_cpart[blockIdx.y][3][j] = a3;
}

__global__ __launch_bounds__(256) void cond_reduce_kernel() {
    int idx = blockIdx.x * 256 + threadIdx.x;
    int bb = idx >> 11, j = idx & 2047;
    float a = 0.f;
    #pragma unroll
    for (int s = 0; s < 16; s++) a += g_cpart[s][bb][j];
    if (j < 1024) g_gain[bb * 1024 + j] = a;
    else          g_shift[bb * 1024 + (j - 1024)] = a;
}

// ---------------- K2: x_cond -> fp16 ----------------
__global__ __launch_bounds__(256) void xcond_kernel(const float* __restrict__ x) {
    int r = blockIdx.x; int b = r >> 10;
    const float* xr = x + (size_t)r * HIDD;
    int e = threadIdx.x * 4;
    float4 v = *(const float4*)(xr + e);
    float ss = v.x * v.x + v.y * v.y + v.z * v.z + v.w * v.w;
    __shared__ float red[32];
    ss = block_reduce_sum(ss, red);
    float rs = rsqrtf(ss * (1.f / 1024.f) + 1e-4f);
    const float* gn = g_gain + b * 1024; const float* sh = g_shift + b * 1024;
    float o0 = v.x * rs * (1.f + gn[e + 0]) + sh[e + 0];
    float o1 = v.y * rs * (1.f + gn[e + 1]) + sh[e + 1];
    float o2 = v.z * rs * (1.f + gn[e + 2]) + sh[e + 2];
    float o3 = v.w * rs * (1.f + gn[e + 3]) + sh[e + 3];
    __half2* dst = (__half2*)(g_xcondh + (size_t)r * HIDD + e);
    dst[0] = __floats2half2_rn(o0, o1);
    dst[1] = __floats2half2_rn(o2, o3);
}

// ---------------- K3: q/k normalization from fp16 qkv ----------------
__global__ __launch_bounds__(256) void qkvnorm_kernel() {
    int r = blockIdx.x; int b = r >> 10, n = r & 1023;
    const __half* row = g_qkvh + (size_t)r * 3072;
    int t = threadIdx.x, e = t * 4, head = t >> 4;
    float2 q01 = __half22float2(*(const __half2*)(row + e));
    float2 q23 = __half22float2(*(const __half2*)(row + e + 2));
    float2 k01 = __half22float2(*(const __half2*)(row + 1024 + e));
    float2 k23 = __half22float2(*(const __half2*)(row + 1024 + e + 2));
    float2 v01 = __half22float2(*(const __half2*)(row + 2048 + e));
    float2 v23 = __half22float2(*(const __half2*)(row + 2048 + e + 2));
    __shared__ float hq[16], hk[16], hv[16];
    if (t < 16) { hq[t] = 0.f; hk[t] = 0.f; hv[t] = 0.f; }
    __syncthreads();
    float sq = q01.x * q01.x + q01.y * q01.y + q23.x * q23.x + q23.y * q23.y;
    float sk = k01.x * k01.x + k01.y * k01.y + k23.x * k23.x + k23.y * k23.y;
    float sv = v01.x * v01.x + v01.y * v01.y + v23.x * v23.x + v23.y * v23.y;
    atomicAdd(&hq[head], sq); atomicAdd(&hk[head], sk); atomicAdd(&hv[head], sv);
    __syncthreads();
    float tq = 0.f, tk = 0.f, tv = 0.f;
    #pragma unroll
    for (int h = 0; h < 16; h++) { tq += hq[h]; tk += hk[h]; tv += hv[h]; }
    float pq = rsqrtf(tq * (1.f / 1024.f) + 1e-4f);
    float pk = rsqrtf(tk * (1.f / 1024.f) + 1e-4f);
    float pv = rsqrtf(tv * (1.f / 1024.f) + 1e-4f);
    float qs = pq * rsqrtf(pq * pq * hq[head] + 1e-6f) * 0.125f;
    float ks = pk * rsqrtf(pk * pk * hk[head] + 1e-6f);
    if (t == 0) g_pv[r] = pv;
    size_t base = ((size_t)(b * 16 + head) * 1024 + n) * 64 + (e & 63);
    __half2* qd = (__half2*)(g_qh + base);
    __half2* kd = (__half2*)(g_kh + base);
    qd[0] = __floats2half2_rn(q01.x * qs, q01.y * qs);
    qd[1] = __floats2half2_rn(q23.x * qs, q23.y * qs);
    kd[0] = __floats2half2_rn(k01.x * ks, k01.y * ks);
    kd[1] = __floats2half2_rn(k23.x * ks, k23.y * ks);
}

// ---------------- V transpose (fp16 in) -> fp16 [bh][d][n] ----------------
__global__ __launch_bounds__(256) void vtrans_kernel() {
    __shared__ float t[32][33];
    int bh = blockIdx.z; int b = bh >> 4, h = bh & 15;
    int n0 = blockIdx.x * 32, d0 = blockIdx.y * 32;
    int tx = threadIdx.x & 31, ty = threadIdx.x >> 5;
    #pragma unroll
    for (int i = 0; i < 32; i += 8) {
        int n = n0 + ty + i;
        int rowg = b * 1024 + n;
        t[ty + i][tx] = __half2float(g_qkvh[(size_t)rowg * 3072 + 2048 + h * 64 + d0 + tx])
                        * g_pv[rowg];
    }
    __syncthreads();
    #pragma unroll
    for (int i = 0; i < 32; i += 8) {
        int d = d0 + ty + i;
        g_vth[((size_t)bh * 64 + d) * 1024 + n0 + tx] = __float2half_rn(t[tx][ty + i]);
    }
}

// ---------------- K4: flash attention via fp16 mma.sync ----------------
#define AT_SROW 36
#define AT_BUF  (64 * AT_SROW)
#define ATT_SMEM_BYTES (4 * AT_BUF * 4)
__global__ __launch_bounds__(128, 4) void attn_mma_kernel() {
    extern __shared__ uint32_t smw[];
    uint32_t* uQ  = smw;
    uint32_t* uK  = smw + AT_BUF;
    uint32_t* uVt = smw + 2 * AT_BUF;
    uint32_t* uP  = smw + 3 * AT_BUF;

    int tid = threadIdx.x;
    int w = tid >> 5, lane = tid & 31;
    int g = lane >> 2, j = lane & 3;
    int bh = blockIdx.y;
    int n0 = blockIdx.x * 64;
    const __half* qb  = g_qh + ((size_t)bh * 1024 + n0) * 64;
    const __half* kb  = g_kh + (size_t)bh * 1024 * 64;
    const __half* vtb = g_vth + (size_t)bh * 64 * 1024;

    #pragma unroll
    for (int i = 0; i < 4; i++) {
        int seg = tid + 128 * i;
        int row = seg >> 3, k8 = seg & 7;
        *(uint4*)(uQ + row * AT_SROW + k8 * 4) = *(const uint4*)(qb + row * 64 + k8 * 8);
    }

    float accO[8][4];
    #pragma unroll
    for (int nt = 0; nt < 8; nt++)
        #pragma unroll
        for (int q = 0; q < 4; q++) accO[nt][q] = 0.f;
    float mi0 = -INFINITY, mi1 = -INFINITY, li0 = 0.f, li1 = 0.f;

    for (int kt = 0; kt < 16; kt++) {
        __syncthreads();
        const __half* kb0 = kb + (size_t)kt * 64 * 64;
        #pragma unroll
        for (int i = 0; i < 4; i++) {
            int seg = tid + 128 * i;
            int row = seg >> 3, k8 = seg & 7;
            *(uint4*)(uK + row * AT_SROW + k8 * 4) = *(const uint4*)(kb0 + row * 64 + k8 * 8);
            *(uint4*)(uVt + row * AT_SROW + k8 * 4) =
                *(const uint4*)(vtb + row * 1024 + kt * 64 + k8 * 8);
        }
        __syncthreads();

        float accS[8][4];
        #pragma unroll
        for (int nt = 0; nt < 8; nt++)
            #pragma unroll
            for (int q = 0; q < 4; q++) accS[nt][q] = 0.f;
        #pragma unroll
        for (int ks = 0; ks < 4; ks++) {
            int k = ks * 8;
            uint32_t a[4];
            int r0 = (w * 16 + g) * AT_SROW, r1 = (w * 16 + g + 8) * AT_SROW;
            a[0] = uQ[r0 + k + j];
            a[1] = uQ[r1 + k + j];
            a[2] = uQ[r0 + k + j + 4];
            a[3] = uQ[r1 + k + j + 4];
            #pragma unroll
            for (int nt = 0; nt < 8; nt++) {
                uint32_t bfr[2];
                bfr[0] = uK[(nt * 8 + g) * AT_SROW + k + j];
                bfr[1] = uK[(nt * 8 + g) * AT_SROW + k + j + 4];
                mma_fp16(accS[nt], a, bfr);
            }
        }

        float mx0 = -INFINITY, mx1 = -INFINITY;
        #pragma unroll
        for (int nt = 0; nt < 8; nt++) {
            mx0 = fmaxf(mx0, fmaxf(accS[nt][0], accS[nt][1]));
            mx1 = fmaxf(mx1, fmaxf(accS[nt][2], accS[nt][3]));
        }
        mx0 = fmaxf(mx0, __shfl_xor_sync(0xffffffffu, mx0, 1));
        mx0 = fmaxf(mx0, __shfl_xor_sync(0xffffffffu, mx0, 2));
        mx1 = fmaxf(mx1, __shfl_xor_sync(0xffffffffu, mx1, 1));
        mx1 = fmaxf(mx1, __shfl_xor_sync(0xffffffffu, mx1, 2));
        float nm0 = fmaxf(mi0, mx0), nm1 = fmaxf(mi1, mx1);
        float corr0 = __expf(mi0 - nm0), corr1 = __expf(mi1 - nm1);
        float ps0 = 0.f, ps1 = 0.f;
        #pragma unroll
        for (int nt = 0; nt < 8; nt++) {
            float p0 = __expf(accS[nt][0] - nm0);
            float p1 = __expf(accS[nt][1] - nm0);
            float p2 = __expf(accS[nt][2] - nm1);
            float p3 = __expf(accS[nt][3] - nm1);
            accS[nt][0] = p0; accS[nt][1] = p1; accS[nt][2] = p2; accS[nt][3] = p3;
            ps0 += p0 + p1; ps1 += p2 + p3;
        }
        ps0 += __shfl_xor_sync(0xffffffffu, ps0, 1);
        ps0 += __shfl_xor_sync(0xffffffffu, ps0, 2);
        ps1 += __shfl_xor_sync(0xffffffffu, ps1, 1);
        ps1 += __shfl_xor_sync(0xffffffffu, ps1, 2);
        li0 = li0 * corr0 + ps0; mi0 = nm0;
        li1 = li1 * corr1 + ps1; mi1 = nm1;
        #pragma unroll
        for (int nt = 0; nt < 8; nt++) {
            accO[nt][0] *= corr0; accO[nt][1] *= corr0;
            accO[nt][2] *= corr1; accO[nt][3] *= corr1;
        }

        #pragma unroll
        for (int nt = 0; nt < 8; nt++) {
            ((__half2*)uP)[(w * 16 + g) * AT_SROW + nt * 4 + j] =
                __floats2half2_rn(accS[nt][0], accS[nt][1]);
            ((__half2*)uP)[(w * 16 + g + 8) * AT_SROW + nt * 4 + j] =
                __floats2half2_rn(accS[nt][2], accS[nt][3]);
        }
        __syncwarp();

        #pragma unroll
        for (int ks = 0; ks < 4; ks++) {
            int k = ks * 8;
            uint32_t a[4];
            int r0 = (w * 16 + g) * AT_SROW, r1 = (w * 16 + g + 8) * AT_SROW;
            a[0] = uP[r0 + k + j];
            a[1] = uP[r1 + k + j];
            a[2] = uP[r0 + k + j + 4];
            a[3] = uP[r1 + k + j + 4];
            #pragma unroll
            for (int nt = 0; nt < 8; nt++) {
                uint32_t bfr[2];
                bfr[0] = uVt[(nt * 8 + g) * AT_SROW + k + j];
                bfr[1] = uVt[(nt * 8 + g) * AT_SROW + k + j + 4];
                mma_fp16(accO[nt], a, bfr);
            }
        }
    }

    float inv0 = 1.f / li0, inv1 = 1.f / li1;
    int b = bh >> 4, h = bh & 15;
    int row0 = b * 1024 + n0 + w * 16 + g;
    #pragma unroll
    for (int nt = 0; nt < 8; nt++) {
        int col = h * 64 + nt * 8 + 2 * j;
        *(__half2*)(g_attnh + (size_t)row0 * HIDD + col) =
            __floats2half2_rn(accO[nt][0] * inv0, accO[nt][1] * inv0);
        *(__half2*)(g_attnh + (size_t)(row0 + 8) * HIDD + col) =
            __floats2half2_rn(accO[nt][2] * inv1, accO[nt][3] * inv1);
    }
}

// ---------------- K5: attn epilogue + residual + second x_cond ----------------
// y from fp16 g_tmph, row SS from 16 GEMM partials.
__global__ __launch_bounds__(256) void post_attn_kernel(const float* __restrict__ x,
                                                        const float* __restrict__ attn_gain) {
    int r = blockIdx.x, b = r >> 10;
    int e = threadIdx.x * 4;
    const __half* yr = g_tmph + (size_t)r * HIDD;
    float2 y01 = __half22float2(*(const __half2*)(yr + e));
    float2 y23 = __half22float2(*(const __half2*)(yr + e + 2));
    float ss = 0.f;
    const float* sp = g_ssp + (size_t)r * 64;
    #pragma unroll
    for (int p = 0; p < 16; p++) ss += sp[p];
    float py = rsqrtf(ss * (1.f / 1024.f) + 1e-4f) * expf(attn_gain[0]);
    float4 xv = *(const float4*)(x + (size_t)r * HIDD + e);
    float4 x1;
    x1.x = (0.7f * xv.x + 0.3f * (y01.x * py)) * RSQRT058;
    x1.y = (0.7f * xv.y + 0.3f * (y01.y * py)) * RSQRT058;
    x1.z = (0.7f * xv.z + 0.3f * (y23.x * py)) * RSQRT058;
    x1.w = (0.7f * xv.w + 0.3f * (y23.y * py)) * RSQRT058;
    *(float4*)(g_x1 + (size_t)r * HIDD + e) = x1;
    __shared__ float red[32];
    float ss1 = x1.x * x1.x + x1.y * x1.y + x1.z * x1.z + x1.w * x1.w;
    ss1 = block_reduce_sum(ss1, red);
    float p1 = rsqrtf(ss1 * (1.f / 1024.f) + 1e-4f);
    const float* gn = g_gain + b * 1024; const float* sh = g_shift + b * 1024;
    float o0 = x1.x * p1 * (1.f + gn[e + 0]) + sh[e + 0];
    float o1 = x1.y * p1 * (1.f + gn[e + 1]) + sh[e + 1];
    float o2 = x1.z * p1 * (1.f + gn[e + 2]) + sh[e + 2];
    float o3 = x1.w * p1 * (1.f + gn[e + 3]) + sh[e + 3];
    __half2* dst = (__half2*)(g_xcondh + (size_t)r * HIDD + e);
    dst[0] = __floats2half2_rn(o0, o1);
    dst[1] = __floats2half2_rn(o2, o3);
}

// ---------------- K6: MLP hidden activation (in-place fp16, SS from 64 partials) ----------------
__global__ __launch_bounds__(256) void mlp_act_kernel() {
    int r = blockIdx.x;
    __half* row = g_hh + (size_t)r * MLPD;
    float ss = 0.f;
    const float* sp = g_ssp + (size_t)r * 64;
    #pragma unroll
    for (int p = 0; p < 64; p++) ss += sp[p];
    float ps = rsqrtf(ss * (1.f / 4096.f) + 1e-4f);
    int e = threadIdx.x * 16;
    uint4 d0 = *(const uint4*)(row + e);
    uint4 d1 = *(const uint4*)(row + e + 8);
    __half2* h0 = (__half2*)&d0;
    __half2* h1 = (__half2*)&d1;
    #pragma unroll
    for (int i = 0; i < 4; i++) {
        float2 a = __half22float2(h0[i]);
        float2 bq = __half22float2(h1[i]);
        float u0 = a.x * ps, u1 = a.y * ps, u2 = bq.x * ps, u3 = bq.y * ps;
        h0[i] = __floats2half2_rn(u0 / (1.f + expf(-u0)) * INV_0596,
                                  u1 / (1.f + expf(-u1)) * INV_0596);
        h1[i] = __floats2half2_rn(u2 / (1.f + expf(-u2)) * INV_0596,
                                  u3 / (1.f + expf(-u3)) * INV_0596);
    }
    *(uint4*)(row + e) = d0;
    *(uint4*)(row + e + 8) = d1;
}

// ---------------- K7: final epilogue ----------------
__global__ __launch_bounds__(256) void final_kernel(const float* __restrict__ mlp_gain,
                                                    float* __restrict__ out) {
    int r = blockIdx.x;
    int e = threadIdx.x * 4;
    const __half* yr = g_tmph + (size_t)r * HIDD;
    float2 y01 = __half22float2(*(const __half2*)(yr + e));
    float2 y23 = __half22float2(*(const __half2*)(yr + e + 2));
    float ss = 0.f;
    const float* sp = g_ssp + (size_t)r * 64;
    #pragma unroll
    for (int p = 0; p < 16; p++) ss += sp[p];
    float pm = rsqrtf(ss * (1.f / 1024.f) + 1e-4f) * expf(mlp_gain[0]);
    float4 x1 = *(const float4*)(g_x1 + (size_t)r * HIDD + e);
    float4 o;
    o.x = (0.7f * x1.x + 0.3f * (y01.x * pm)) * RSQRT058;
    o.y = (0.7f * x1.y + 0.3f * (y01.y * pm)) * RSQRT058;
    o.z = (0.7f * x1.z + 0.3f * (y23.x * pm)) * RSQRT058;
    o.w = (0.7f * x1.w + 0.3f * (y23.y * pm)) * RSQRT058;
    *(float4*)(out + (size_t)r * HIDD + e) = o;
}

// ---------------- launch ----------------
extern "C" void kernel_launch(void* const* d_in, const int* in_sizes, int n_in,
                              void* d_out, int out_size) {
    const float* x        = (const float*)d_in[0];
    const float* c        = (const float*)d_in[1];
    const float* w_cond   = (const float*)d_in[2];
    const float* w_qkv    = (const float*)d_in[3];
    const float* w_out    = (const float*)d_in[4];
    const float* w_mlp1   = (const float*)d_in[5];
    const float* w_mlp2   = (const float*)d_in[6];
    const float* attn_gain = (const float*)d_in[7];
    const float* mlp_gain  = (const float*)d_in[8];
    float* out = (float*)d_out;

    void* p;
    cudaGetSymbolAddress(&p, g_xcondh); __half* xcondh = (__half*)p;
    cudaGetSymbolAddress(&p, g_qkvh);   __half* qkvh  = (__half*)p;
    cudaGetSymbolAddress(&p, g_attnh);  __half* attnh = (__half*)p;
    cudaGetSymbolAddress(&p, g_tmph);   __half* tmph  = (__half*)p;
    cudaGetSymbolAddress(&p, g_hh);     __half* hh    = (__half*)p;
    cudaGetSymbolAddress(&p, g_ssp);    float* ssp    = (float*)p;
    cudaGetSymbolAddress(&p, g_s_qkv);  float* sqkv   = (float*)p;
    cudaGetSymbolAddress(&p, g_s_out);  float* sout   = (float*)p;
    cudaGetSymbolAddress(&p, g_s_mlp1); float* smlp1  = (float*)p;
    cudaGetSymbolAddress(&p, g_s_mlp2); float* smlp2  = (float*)p;
    cudaGetSymbolAddress(&p, g_wtq);    __half* wtq   = (__half*)p;
    cudaGetSymbolAddress(&p, g_wto);    __half* wto   = (__half*)p;
    cudaGetSymbolAddress(&p, g_wt1);    __half* wt1   = (__half*)p;
    cudaGetSymbolAddress(&p, g_wt2);    __half* wt2   = (__half*)p;

    cudaFuncSetAttribute(attn_mma_kernel, cudaFuncAttributeMaxDynamicSharedMemorySize,
                         ATT_SMEM_BYTES);
    cudaFuncSetAttribute(gemm_mma_kernel, cudaFuncAttributeMaxDynamicSharedMemorySize,
                         GEMM_SMEM_BYTES);

    scales_kernel<<<8192, 128>>>(w_cond, w_qkv, w_out, w_mlp1, w_mlp2);
    cond_part_kernel<<<dim3(8, 16), 256>>>(c, w_cond);
    cond_reduce_kernel<<<32, 256>>>();
    transpose_scale_kernel<<<dim3(3072 / 32, 1024 / 32), 256>>>(w_qkv, sqkv, wtq, 1024, 3072);
    transpose_scale_kernel<<<dim3(1024 / 32, 1024 / 32), 256>>>(w_out, sout, wto, 1024, 1024);
    transpose_scale_kernel<<<dim3(4096 / 32, 1024 / 32), 256>>>(w_mlp1, smlp1, wt1, 1024, 4096);
    transpose_scale_kernel<<<dim3(1024 / 32, 4096 / 32), 256>>>(w_mlp2, smlp2, wt2, 4096, 1024);

    xcond_kernel<<<4096, 256>>>(x);
    gemm_mma_kernel<<<dim3(12, 32), 256, GEMM_SMEM_BYTES>>>(xcondh, wtq, qkvh, nullptr,
                                                            4096, 3072, 1024);
    qkvnorm_kernel<<<4096, 256>>>();
    vtrans_kernel<<<dim3(32, 2, 64), 256>>>();
    attn_mma_kernel<<<dim3(16, 64), 128, ATT_SMEM_BYTES>>>();
    gemm_mma_kernel<<<dim3(4, 32), 256, GEMM_SMEM_BYTES>>>(attnh, wto, tmph, ssp,
                                                           4096, 1024, 1024);
    post_attn_kernel<<<4096, 256>>>(x, attn_gain);
    gemm_mma_kernel<<<dim3(16, 32), 256, GEMM_SMEM_BYTES>>>(xcondh, wt1, hh, ssp,
                                                            4096, 4096, 1024);
    mlp_act_kernel<<<4096, 256>>>();
    gemm_mma_kernel<<<dim3(4, 32), 256, GEMM_SMEM_BYTES>>>(hh, wt2, tmph, ssp,
                                                           4096, 1024, 4096);
    final_kernel<<<4096, 256>>>(mlp_gain, out);
}